// round 1
// baseline (speedup 1.0000x reference)
#include <cuda_runtime.h>
#include <cuda_bf16.h>
#include <math.h>

// Problem constants
#define BATCH 2
#define SEQ   2048
#define DMODEL 1024
#define NHEAD 16
#define HDIM  64
#define FFDIM 4096
#define MROWS (BATCH*SEQ)   // 4096
#define LN_EPS 1e-5f

// ---------------- scratch buffers (static device allocs are allowed) -------
__device__ float g_xn [MROWS*DMODEL];
__device__ float g_q  [MROWS*DMODEL];
__device__ float g_k  [MROWS*DMODEL];
__device__ float g_v  [MROWS*DMODEL];
__device__ float g_at [MROWS*DMODEL];
__device__ float g_r1 [MROWS*DMODEL];
__device__ float g_y  [MROWS*DMODEL];
__device__ float g_h  [MROWS*FFDIM];

// ---------------- LayerNorm: one block per row, D=1024 ---------------------
__global__ __launch_bounds__(256)
void ln_kernel(const float* __restrict__ x, const float* __restrict__ g,
               const float* __restrict__ b, float* __restrict__ y)
{
    int row = blockIdx.x;
    int tid = threadIdx.x;
    const float4* xr = reinterpret_cast<const float4*>(x + (size_t)row * DMODEL);
    float4 v = xr[tid];

    float s = v.x + v.y + v.z + v.w;
    float q = v.x*v.x + v.y*v.y + v.z*v.z + v.w*v.w;

    // warp reduce
    #pragma unroll
    for (int o = 16; o > 0; o >>= 1) {
        s += __shfl_down_sync(0xffffffffu, s, o);
        q += __shfl_down_sync(0xffffffffu, q, o);
    }
    __shared__ float ss[8], sq[8];
    int wid = tid >> 5, lane = tid & 31;
    if (lane == 0) { ss[wid] = s; sq[wid] = q; }
    __syncthreads();
    float tot = 0.f, totq = 0.f;
    #pragma unroll
    for (int i = 0; i < 8; ++i) { tot += ss[i]; totq += sq[i]; }

    float mu  = tot * (1.0f / DMODEL);
    float var = totq * (1.0f / DMODEL) - mu * mu;
    float rs  = rsqrtf(var + LN_EPS);

    float4 gg = reinterpret_cast<const float4*>(g)[tid];
    float4 bb = reinterpret_cast<const float4*>(b)[tid];
    float4 o;
    o.x = (v.x - mu) * rs * gg.x + bb.x;
    o.y = (v.y - mu) * rs * gg.y + bb.y;
    o.z = (v.z - mu) * rs * gg.z + bb.z;
    o.w = (v.w - mu) * rs * gg.w + bb.w;
    reinterpret_cast<float4*>(y + (size_t)row * DMODEL)[tid] = o;
}

// ---------------- GEMM: C[M,N] = A[M,K] @ W[N,K]^T + bias (+res / gelu) ----
// 64x64 tile, BK=16, 256 threads, 4x4 microtile.
#define EPI_BIAS 0
#define EPI_RES  1
#define EPI_GELU 2

__device__ __forceinline__ float gelu_exact(float v) {
    return 0.5f * v * (1.0f + erff(v * 0.70710678118654752440f));
}

template<int EPI>
__global__ __launch_bounds__(256)
void gemm_kernel(const float* __restrict__ A, const float* __restrict__ W,
                 const float* __restrict__ bias, const float* __restrict__ res,
                 float* __restrict__ C, int M, int N, int K)
{
    __shared__ float As[16 * 64];
    __shared__ float Ws[16 * 64];

    int tid = threadIdx.x;
    int tx = tid & 15, ty = tid >> 4;
    int n0 = blockIdx.x * 64;
    int m0 = blockIdx.y * 64;

    int lr = tid >> 2;       // 0..63
    int lc = tid & 3;        // 0..3  (k-chunk of 4 floats)

    const float* Ap = A + (size_t)(m0 + lr) * K + lc * 4;
    const float* Wp = W + (size_t)(n0 + lr) * K + lc * 4;

    float c[4][4];
    #pragma unroll
    for (int i = 0; i < 4; ++i)
        #pragma unroll
        for (int j = 0; j < 4; ++j) c[i][j] = 0.f;

    for (int k0 = 0; k0 < K; k0 += 16) {
        float4 a4 = *reinterpret_cast<const float4*>(Ap + k0);
        float4 w4 = *reinterpret_cast<const float4*>(Wp + k0);
        __syncthreads();
        As[(lc*4+0)*64 + lr] = a4.x;
        As[(lc*4+1)*64 + lr] = a4.y;
        As[(lc*4+2)*64 + lr] = a4.z;
        As[(lc*4+3)*64 + lr] = a4.w;
        Ws[(lc*4+0)*64 + lr] = w4.x;
        Ws[(lc*4+1)*64 + lr] = w4.y;
        Ws[(lc*4+2)*64 + lr] = w4.z;
        Ws[(lc*4+3)*64 + lr] = w4.w;
        __syncthreads();

        #pragma unroll
        for (int k = 0; k < 16; ++k) {
            float4 a = *reinterpret_cast<float4*>(&As[k*64 + ty*4]);
            float4 w = *reinterpret_cast<float4*>(&Ws[k*64 + tx*4]);
            c[0][0] += a.x*w.x; c[0][1] += a.x*w.y; c[0][2] += a.x*w.z; c[0][3] += a.x*w.w;
            c[1][0] += a.y*w.x; c[1][1] += a.y*w.y; c[1][2] += a.y*w.z; c[1][3] += a.y*w.w;
            c[2][0] += a.z*w.x; c[2][1] += a.z*w.y; c[2][2] += a.z*w.z; c[2][3] += a.z*w.w;
            c[3][0] += a.w*w.x; c[3][1] += a.w*w.y; c[3][2] += a.w*w.z; c[3][3] += a.w*w.w;
        }
    }

    float4 bv = *reinterpret_cast<const float4*>(&bias[n0 + tx*4]);
    float bvv[4] = {bv.x, bv.y, bv.z, bv.w};

    #pragma unroll
    for (int i = 0; i < 4; ++i) {
        int row = m0 + ty*4 + i;
        float4 o;
        float vals[4];
        #pragma unroll
        for (int j = 0; j < 4; ++j) vals[j] = c[i][j] + bvv[j];
        if (EPI == EPI_RES) {
            float4 rv = *reinterpret_cast<const float4*>(&res[(size_t)row * N + n0 + tx*4]);
            vals[0] += rv.x; vals[1] += rv.y; vals[2] += rv.z; vals[3] += rv.w;
        } else if (EPI == EPI_GELU) {
            #pragma unroll
            for (int j = 0; j < 4; ++j) vals[j] = gelu_exact(vals[j]);
        }
        o.x = vals[0]; o.y = vals[1]; o.z = vals[2]; o.w = vals[3];
        *reinterpret_cast<float4*>(&C[(size_t)row * N + n0 + tx*4]) = o;
    }
}

// ---------------- Flash attention -----------------------------------------
// grid.x = S/64 (q tiles), grid.y = B*H. 256 threads.
// thread: query row r = tid/4 within tile, key group g = tid%3.. (tid&3) of 16 keys.
#define SMSTRIDE 68
#define ATTN_SMEM (3 * 64 * SMSTRIDE * 4)

__global__ __launch_bounds__(256)
void attn_kernel(const float* __restrict__ Q, const float* __restrict__ K,
                 const float* __restrict__ V, float* __restrict__ O)
{
    extern __shared__ float sm[];
    float* Qs = sm;
    float* Ks = sm + 64 * SMSTRIDE;
    float* Vs = Ks + 64 * SMSTRIDE;

    int tid = threadIdx.x;
    int bh = blockIdx.y;
    int b = bh >> 4, h = bh & 15;
    int qbase  = b * SEQ + blockIdx.x * 64;   // global row of first query
    int kvbase = b * SEQ;
    int hcol   = h * HDIM;

    // load Q tile: 64 rows x 64 cols
    #pragma unroll
    for (int i = tid; i < 64 * 16; i += 256) {
        int row = i >> 4, c4 = i & 15;
        float4 t = *reinterpret_cast<const float4*>(&Q[(size_t)(qbase + row) * DMODEL + hcol + c4*4]);
        *reinterpret_cast<float4*>(&Qs[row * SMSTRIDE + c4*4]) = t;
    }

    int r = tid >> 2;   // query row 0..63
    int g = tid & 3;    // key group: keys g*16 .. g*16+15

    float m_i = -1e30f, l_i = 0.f;
    float acc[64];
    #pragma unroll
    for (int d = 0; d < 64; ++d) acc[d] = 0.f;

    const float scale = 0.125f;  // 1/sqrt(64)

    for (int t = 0; t < SEQ / 64; ++t) {
        __syncthreads();
        #pragma unroll
        for (int i = tid; i < 64 * 16; i += 256) {
            int row = i >> 4, c4 = i & 15;
            size_t gidx = (size_t)(kvbase + t*64 + row) * DMODEL + hcol + c4*4;
            *reinterpret_cast<float4*>(&Ks[row * SMSTRIDE + c4*4]) =
                *reinterpret_cast<const float4*>(&K[gidx]);
            *reinterpret_cast<float4*>(&Vs[row * SMSTRIDE + c4*4]) =
                *reinterpret_cast<const float4*>(&V[gidx]);
        }
        __syncthreads();

        // scores: s[j] = q_r . k_{g*16+j}
        float s[16];
        #pragma unroll
        for (int j = 0; j < 16; ++j) s[j] = 0.f;
        #pragma unroll
        for (int dc = 0; dc < 16; ++dc) {
            float4 q4 = *reinterpret_cast<float4*>(&Qs[r * SMSTRIDE + dc*4]);
            #pragma unroll
            for (int j = 0; j < 16; ++j) {
                float4 k4 = *reinterpret_cast<float4*>(&Ks[(g*16 + j) * SMSTRIDE + dc*4]);
                s[j] += q4.x*k4.x + q4.y*k4.y + q4.z*k4.z + q4.w*k4.w;
            }
        }

        // online softmax over the 64 keys of this tile (4 lanes per row)
        float mnew = m_i;
        #pragma unroll
        for (int j = 0; j < 16; ++j) { s[j] *= scale; mnew = fmaxf(mnew, s[j]); }
        mnew = fmaxf(mnew, __shfl_xor_sync(0xffffffffu, mnew, 1));
        mnew = fmaxf(mnew, __shfl_xor_sync(0xffffffffu, mnew, 2));

        float alpha = __expf(m_i - mnew);
        float lsum = 0.f;
        #pragma unroll
        for (int j = 0; j < 16; ++j) { s[j] = __expf(s[j] - mnew); lsum += s[j]; }
        lsum += __shfl_xor_sync(0xffffffffu, lsum, 1);
        lsum += __shfl_xor_sync(0xffffffffu, lsum, 2);
        l_i = l_i * alpha + lsum;
        m_i = mnew;

        #pragma unroll
        for (int d = 0; d < 64; ++d) acc[d] *= alpha;

        // acc[d] += sum_j p[j] * V[g*16+j][d]
        #pragma unroll
        for (int dc = 0; dc < 16; ++dc) {
            #pragma unroll
            for (int j = 0; j < 16; ++j) {
                float4 v4 = *reinterpret_cast<float4*>(&Vs[(g*16 + j) * SMSTRIDE + dc*4]);
                acc[dc*4+0] += s[j] * v4.x;
                acc[dc*4+1] += s[j] * v4.y;
                acc[dc*4+2] += s[j] * v4.z;
                acc[dc*4+3] += s[j] * v4.w;
            }
        }
    }

    // combine partial sums across the 4 lanes of each row, normalize, write
    float inv_l = 1.0f / l_i;
    float fin[16];
    #pragma unroll
    for (int d = 0; d < 64; ++d) {
        float vsum = acc[d];
        vsum += __shfl_xor_sync(0xffffffffu, vsum, 1);
        vsum += __shfl_xor_sync(0xffffffffu, vsum, 2);
        if ((d >> 4) == g) fin[d & 15] = vsum * inv_l;
    }
    float* orow = O + (size_t)(qbase + r) * DMODEL + hcol + g*16;
    #pragma unroll
    for (int c4 = 0; c4 < 4; ++c4) {
        float4 o;
        o.x = fin[c4*4+0]; o.y = fin[c4*4+1]; o.z = fin[c4*4+2]; o.w = fin[c4*4+3];
        reinterpret_cast<float4*>(orow)[c4] = o;
    }
}

// ---------------- launch ----------------------------------------------------
extern "C" void kernel_launch(void* const* d_in, const int* in_sizes, int n_in,
                              void* d_out, int out_size)
{
    const float* x    = (const float*)d_in[0];
    const float* wq   = (const float*)d_in[1];
    const float* bq   = (const float*)d_in[2];
    const float* wk   = (const float*)d_in[3];
    const float* bk   = (const float*)d_in[4];
    const float* wv   = (const float*)d_in[5];
    const float* bv   = (const float*)d_in[6];
    const float* wo   = (const float*)d_in[7];
    const float* bo   = (const float*)d_in[8];
    const float* ln1g = (const float*)d_in[9];
    const float* ln1b = (const float*)d_in[10];
    const float* w1   = (const float*)d_in[11];
    const float* b1   = (const float*)d_in[12];
    const float* w2   = (const float*)d_in[13];
    const float* b2   = (const float*)d_in[14];
    const float* ln2g = (const float*)d_in[15];
    const float* ln2b = (const float*)d_in[16];
    float* out = (float*)d_out;

    float *xn, *q, *k, *v, *at, *r1, *y, *h;
    cudaGetSymbolAddress((void**)&xn, g_xn);
    cudaGetSymbolAddress((void**)&q,  g_q);
    cudaGetSymbolAddress((void**)&k,  g_k);
    cudaGetSymbolAddress((void**)&v,  g_v);
    cudaGetSymbolAddress((void**)&at, g_at);
    cudaGetSymbolAddress((void**)&r1, g_r1);
    cudaGetSymbolAddress((void**)&y,  g_y);
    cudaGetSymbolAddress((void**)&h,  g_h);

    cudaFuncSetAttribute(attn_kernel, cudaFuncAttributeMaxDynamicSharedMemorySize, ATTN_SMEM);

    dim3 gD(DMODEL/64, MROWS/64);   // N=1024 GEMMs
    dim3 gF(FFDIM/64,  MROWS/64);   // N=4096 GEMM

    // xn = LN1(x)
    ln_kernel<<<MROWS, 256>>>(x, ln1g, ln1b, xn);
    // q,k,v
    gemm_kernel<EPI_BIAS><<<gD, 256>>>(xn, wq, bq, nullptr, q, MROWS, DMODEL, DMODEL);
    gemm_kernel<EPI_BIAS><<<gD, 256>>>(xn, wk, bk, nullptr, k, MROWS, DMODEL, DMODEL);
    gemm_kernel<EPI_BIAS><<<gD, 256>>>(xn, wv, bv, nullptr, v, MROWS, DMODEL, DMODEL);
    // attention
    attn_kernel<<<dim3(SEQ/64, BATCH*NHEAD), 256, ATTN_SMEM>>>(q, k, v, at);
    // r1 = xn + at @ wo^T + bo
    gemm_kernel<EPI_RES><<<gD, 256>>>(at, wo, bo, xn, r1, MROWS, DMODEL, DMODEL);
    // y = LN2(r1)
    ln_kernel<<<MROWS, 256>>>(r1, ln2g, ln2b, y);
    // h = gelu(y @ w1^T + b1)
    gemm_kernel<EPI_GELU><<<gF, 256>>>(y, w1, b1, nullptr, h, MROWS, FFDIM, DMODEL);
    // out = y + h @ w2^T + b2
    gemm_kernel<EPI_RES><<<gD, 256>>>(h, w2, b2, y, out, MROWS, DMODEL, FFDIM);
}

// round 2
// speedup vs baseline: 2.1079x; 2.1079x over previous
#include <cuda_runtime.h>
#include <cuda_bf16.h>
#include <math.h>

// Problem constants
#define BATCH 2
#define SEQ   2048
#define DMODEL 1024
#define NHEAD 16
#define HDIM  64
#define FFDIM 4096
#define MROWS (BATCH*SEQ)   // 4096
#define LN_EPS 1e-5f

// ---------------- scratch buffers ------------------------------------------
__device__ float g_xn [MROWS*DMODEL];
__device__ float g_q  [MROWS*DMODEL];
__device__ float g_k  [MROWS*DMODEL];
__device__ float g_v  [MROWS*DMODEL];
__device__ float g_at [MROWS*DMODEL];
__device__ float g_r1 [MROWS*DMODEL];
__device__ float g_y  [MROWS*DMODEL];
__device__ float g_h  [MROWS*FFDIM];

// ---------------- LayerNorm: one block per row, D=1024 ---------------------
__global__ __launch_bounds__(256)
void ln_kernel(const float* __restrict__ x, const float* __restrict__ g,
               const float* __restrict__ b, float* __restrict__ y)
{
    int row = blockIdx.x;
    int tid = threadIdx.x;
    const float4* xr = reinterpret_cast<const float4*>(x + (size_t)row * DMODEL);
    float4 v = xr[tid];

    float s = v.x + v.y + v.z + v.w;
    float q = v.x*v.x + v.y*v.y + v.z*v.z + v.w*v.w;

    #pragma unroll
    for (int o = 16; o > 0; o >>= 1) {
        s += __shfl_down_sync(0xffffffffu, s, o);
        q += __shfl_down_sync(0xffffffffu, q, o);
    }
    __shared__ float ss[8], sq[8];
    int wid = tid >> 5, lane = tid & 31;
    if (lane == 0) { ss[wid] = s; sq[wid] = q; }
    __syncthreads();
    float tot = 0.f, totq = 0.f;
    #pragma unroll
    for (int i = 0; i < 8; ++i) { tot += ss[i]; totq += sq[i]; }

    float mu  = tot * (1.0f / DMODEL);
    float var = totq * (1.0f / DMODEL) - mu * mu;
    float rs  = rsqrtf(var + LN_EPS);

    float4 gg = reinterpret_cast<const float4*>(g)[tid];
    float4 bb = reinterpret_cast<const float4*>(b)[tid];
    float4 o;
    o.x = (v.x - mu) * rs * gg.x + bb.x;
    o.y = (v.y - mu) * rs * gg.y + bb.y;
    o.z = (v.z - mu) * rs * gg.z + bb.z;
    o.w = (v.w - mu) * rs * gg.w + bb.w;
    reinterpret_cast<float4*>(y + (size_t)row * DMODEL)[tid] = o;
}

// ---------------- GEMM: C[M,N] = A[M,K] @ W[N,K]^T + bias (+res / gelu) ----
// 128x128 tile, BK=16, 256 threads, 8x8 microtile, reg-prefetch.
#define EPI_BIAS 0
#define EPI_RES  1
#define EPI_GELU 2
#define SST 132   // smem row stride (floats) for 128-wide tiles

__device__ __forceinline__ float gelu_exact(float v) {
    return 0.5f * v * (1.0f + erff(v * 0.70710678118654752440f));
}

template<int EPI>
__global__ __launch_bounds__(256, 2)
void gemm_kernel(const float* __restrict__ A, const float* __restrict__ W,
                 const float* __restrict__ bias, const float* __restrict__ res,
                 float* __restrict__ C, int M, int N, int K)
{
    __shared__ float As[16 * SST];
    __shared__ float Ws[16 * SST];

    int t  = threadIdx.x;
    int tx = t & 15, ty = t >> 4;
    int n0 = blockIdx.x * 128;
    int m0 = blockIdx.y * 128;

    int lr = t >> 2;        // 0..63
    int c4 = t & 3;         // k-chunk of 4 floats

    const float* Ap = A + (size_t)(m0 + lr) * K + c4 * 4;
    const float* Wp = W + (size_t)(n0 + lr) * K + c4 * 4;
    size_t row64 = (size_t)64 * K;

    float acc[8][8];
    #pragma unroll
    for (int i = 0; i < 8; ++i)
        #pragma unroll
        for (int j = 0; j < 8; ++j) acc[i][j] = 0.f;

    float4 a0v = *reinterpret_cast<const float4*>(Ap);
    float4 a1v = *reinterpret_cast<const float4*>(Ap + row64);
    float4 w0v = *reinterpret_cast<const float4*>(Wp);
    float4 w1v = *reinterpret_cast<const float4*>(Wp + row64);

    for (int k0 = 0; k0 < K; k0 += 16) {
        __syncthreads();
        As[(c4*4+0)*SST + lr]      = a0v.x;
        As[(c4*4+1)*SST + lr]      = a0v.y;
        As[(c4*4+2)*SST + lr]      = a0v.z;
        As[(c4*4+3)*SST + lr]      = a0v.w;
        As[(c4*4+0)*SST + 64 + lr] = a1v.x;
        As[(c4*4+1)*SST + 64 + lr] = a1v.y;
        As[(c4*4+2)*SST + 64 + lr] = a1v.z;
        As[(c4*4+3)*SST + 64 + lr] = a1v.w;
        Ws[(c4*4+0)*SST + lr]      = w0v.x;
        Ws[(c4*4+1)*SST + lr]      = w0v.y;
        Ws[(c4*4+2)*SST + lr]      = w0v.z;
        Ws[(c4*4+3)*SST + lr]      = w0v.w;
        Ws[(c4*4+0)*SST + 64 + lr] = w1v.x;
        Ws[(c4*4+1)*SST + 64 + lr] = w1v.y;
        Ws[(c4*4+2)*SST + 64 + lr] = w1v.z;
        Ws[(c4*4+3)*SST + 64 + lr] = w1v.w;
        __syncthreads();

        if (k0 + 16 < K) {
            a0v = *reinterpret_cast<const float4*>(Ap + k0 + 16);
            a1v = *reinterpret_cast<const float4*>(Ap + row64 + k0 + 16);
            w0v = *reinterpret_cast<const float4*>(Wp + k0 + 16);
            w1v = *reinterpret_cast<const float4*>(Wp + row64 + k0 + 16);
        }

        #pragma unroll
        for (int k = 0; k < 16; ++k) {
            float4 a0 = *reinterpret_cast<float4*>(&As[k*SST + ty*4]);
            float4 a1 = *reinterpret_cast<float4*>(&As[k*SST + 64 + ty*4]);
            float4 w0 = *reinterpret_cast<float4*>(&Ws[k*SST + tx*4]);
            float4 w1 = *reinterpret_cast<float4*>(&Ws[k*SST + 64 + tx*4]);
            float av[8] = {a0.x,a0.y,a0.z,a0.w,a1.x,a1.y,a1.z,a1.w};
            float wv[8] = {w0.x,w0.y,w0.z,w0.w,w1.x,w1.y,w1.z,w1.w};
            #pragma unroll
            for (int i = 0; i < 8; ++i)
                #pragma unroll
                for (int j = 0; j < 8; ++j)
                    acc[i][j] += av[i] * wv[j];
        }
    }

    float4 b0 = *reinterpret_cast<const float4*>(&bias[n0 + tx*4]);
    float4 b1 = *reinterpret_cast<const float4*>(&bias[n0 + 64 + tx*4]);
    float bvv[8] = {b0.x,b0.y,b0.z,b0.w,b1.x,b1.y,b1.z,b1.w};

    #pragma unroll
    for (int i = 0; i < 8; ++i) {
        int row = m0 + ((i < 4) ? (ty*4 + i) : (64 + ty*4 + i - 4));
        #pragma unroll
        for (int jb = 0; jb < 2; ++jb) {
            int col = n0 + jb*64 + tx*4;
            float vals[4];
            #pragma unroll
            for (int j = 0; j < 4; ++j) vals[j] = acc[i][jb*4+j] + bvv[jb*4+j];
            if (EPI == EPI_RES) {
                float4 rv = *reinterpret_cast<const float4*>(&res[(size_t)row * N + col]);
                vals[0] += rv.x; vals[1] += rv.y; vals[2] += rv.z; vals[3] += rv.w;
            } else if (EPI == EPI_GELU) {
                #pragma unroll
                for (int j = 0; j < 4; ++j) vals[j] = gelu_exact(vals[j]);
            }
            float4 o; o.x = vals[0]; o.y = vals[1]; o.z = vals[2]; o.w = vals[3];
            *reinterpret_cast<float4*>(&C[(size_t)row * N + col]) = o;
        }
    }
}

// ---------------- Flash attention -----------------------------------------
// grid.x = S/64 (q tiles), grid.y = B*H. 256 threads.
// thread: query row r = tid>>2; lane quad slot g = tid&3.
//   scores: lane g handles keys {4j+g, j=0..15}  (consecutive smem rows per quad)
//   PV:     lane g accumulates dims [g*16, g*16+16) over ALL 64 keys,
//           p distributed via quad shuffle. acc[16] per thread, no final reduce.
#define AST 68
#define ATTN_SMEM (3 * 64 * AST * 4)

__global__ __launch_bounds__(256)
void attn_kernel(const float* __restrict__ Q, const float* __restrict__ K,
                 const float* __restrict__ V, float* __restrict__ O)
{
    extern __shared__ float sm[];
    float* Qs = sm;
    float* Ks = sm + 64 * AST;
    float* Vs = Ks + 64 * AST;

    int tid = threadIdx.x;
    int bh = blockIdx.y;
    int b = bh >> 4, h = bh & 15;
    int qbase  = b * SEQ + blockIdx.x * 64;
    int kvbase = b * SEQ;
    int hcol   = h * HDIM;

    // load Q tile: 64 rows x 64 cols
    #pragma unroll
    for (int i = tid; i < 64 * 16; i += 256) {
        int row = i >> 4, cc = i & 15;
        float4 tq = *reinterpret_cast<const float4*>(&Q[(size_t)(qbase + row) * DMODEL + hcol + cc*4]);
        *reinterpret_cast<float4*>(&Qs[row * AST + cc*4]) = tq;
    }

    int r = tid >> 2;       // query row 0..63
    int g = tid & 3;        // quad slot
    int lane = tid & 31;
    int qb = lane & 28;     // quad base lane

    float m_i = -1e30f, l_i = 0.f;
    float s[16];
    float acc[16];
    #pragma unroll
    for (int d = 0; d < 16; ++d) acc[d] = 0.f;

    const float scale = 0.125f;  // 1/sqrt(64)

    for (int t = 0; t < SEQ / 64; ++t) {
        __syncthreads();
        #pragma unroll
        for (int i = tid; i < 64 * 16; i += 256) {
            int row = i >> 4, cc = i & 15;
            size_t gidx = (size_t)(kvbase + t*64 + row) * DMODEL + hcol + cc*4;
            *reinterpret_cast<float4*>(&Ks[row * AST + cc*4]) =
                *reinterpret_cast<const float4*>(&K[gidx]);
            *reinterpret_cast<float4*>(&Vs[row * AST + cc*4]) =
                *reinterpret_cast<const float4*>(&V[gidx]);
        }
        __syncthreads();

        // scores for keys 4j+g
        #pragma unroll
        for (int j = 0; j < 16; ++j) s[j] = 0.f;
        #pragma unroll
        for (int dc = 0; dc < 16; ++dc) {
            float4 q4 = *reinterpret_cast<float4*>(&Qs[r * AST + dc*4]);
            #pragma unroll
            for (int j = 0; j < 16; ++j) {
                float4 k4 = *reinterpret_cast<float4*>(&Ks[(4*j + g) * AST + dc*4]);
                s[j] += q4.x*k4.x + q4.y*k4.y + q4.z*k4.z + q4.w*k4.w;
            }
        }

        // online softmax (quad = one query row)
        float mnew = m_i;
        #pragma unroll
        for (int j = 0; j < 16; ++j) { s[j] *= scale; mnew = fmaxf(mnew, s[j]); }
        mnew = fmaxf(mnew, __shfl_xor_sync(0xffffffffu, mnew, 1));
        mnew = fmaxf(mnew, __shfl_xor_sync(0xffffffffu, mnew, 2));

        float alpha = __expf(m_i - mnew);
        float lsum = 0.f;
        #pragma unroll
        for (int j = 0; j < 16; ++j) { s[j] = __expf(s[j] - mnew); lsum += s[j]; }
        lsum += __shfl_xor_sync(0xffffffffu, lsum, 1);
        lsum += __shfl_xor_sync(0xffffffffu, lsum, 2);
        l_i = l_i * alpha + lsum;
        m_i = mnew;

        #pragma unroll
        for (int d = 0; d < 16; ++d) acc[d] *= alpha;

        // PV: all 64 keys, dims g*16..g*16+15
        #pragma unroll
        for (int kk = 0; kk < 64; ++kk) {
            float p = __shfl_sync(0xffffffffu, s[kk >> 2], qb | (kk & 3));
            const float* vrow = &Vs[kk * AST + g*16];
            float4 v0 = *reinterpret_cast<const float4*>(vrow);
            float4 v1 = *reinterpret_cast<const float4*>(vrow + 4);
            float4 v2 = *reinterpret_cast<const float4*>(vrow + 8);
            float4 v3 = *reinterpret_cast<const float4*>(vrow + 12);
            acc[0]  += p*v0.x; acc[1]  += p*v0.y; acc[2]  += p*v0.z; acc[3]  += p*v0.w;
            acc[4]  += p*v1.x; acc[5]  += p*v1.y; acc[6]  += p*v1.z; acc[7]  += p*v1.w;
            acc[8]  += p*v2.x; acc[9]  += p*v2.y; acc[10] += p*v2.z; acc[11] += p*v2.w;
            acc[12] += p*v3.x; acc[13] += p*v3.y; acc[14] += p*v3.z; acc[15] += p*v3.w;
        }
    }

    float inv_l = 1.0f / l_i;
    float* orow = O + (size_t)(qbase + r) * DMODEL + hcol + g*16;
    #pragma unroll
    for (int cc = 0; cc < 4; ++cc) {
        float4 o;
        o.x = acc[cc*4+0]*inv_l; o.y = acc[cc*4+1]*inv_l;
        o.z = acc[cc*4+2]*inv_l; o.w = acc[cc*4+3]*inv_l;
        reinterpret_cast<float4*>(orow)[cc] = o;
    }
}

// ---------------- launch ----------------------------------------------------
extern "C" void kernel_launch(void* const* d_in, const int* in_sizes, int n_in,
                              void* d_out, int out_size)
{
    const float* x    = (const float*)d_in[0];
    const float* wq   = (const float*)d_in[1];
    const float* bq   = (const float*)d_in[2];
    const float* wk   = (const float*)d_in[3];
    const float* bk   = (const float*)d_in[4];
    const float* wv   = (const float*)d_in[5];
    const float* bv   = (const float*)d_in[6];
    const float* wo   = (const float*)d_in[7];
    const float* bo   = (const float*)d_in[8];
    const float* ln1g = (const float*)d_in[9];
    const float* ln1b = (const float*)d_in[10];
    const float* w1   = (const float*)d_in[11];
    const float* b1   = (const float*)d_in[12];
    const float* w2   = (const float*)d_in[13];
    const float* b2   = (const float*)d_in[14];
    const float* ln2g = (const float*)d_in[15];
    const float* ln2b = (const float*)d_in[16];
    float* out = (float*)d_out;

    float *xn, *q, *k, *v, *at, *r1, *y, *h;
    cudaGetSymbolAddress((void**)&xn, g_xn);
    cudaGetSymbolAddress((void**)&q,  g_q);
    cudaGetSymbolAddress((void**)&k,  g_k);
    cudaGetSymbolAddress((void**)&v,  g_v);
    cudaGetSymbolAddress((void**)&at, g_at);
    cudaGetSymbolAddress((void**)&r1, g_r1);
    cudaGetSymbolAddress((void**)&y,  g_y);
    cudaGetSymbolAddress((void**)&h,  g_h);

    cudaFuncSetAttribute(attn_kernel, cudaFuncAttributeMaxDynamicSharedMemorySize, ATTN_SMEM);

    dim3 gD(DMODEL/128, MROWS/128);   // N=1024 GEMMs: 8x32
    dim3 gF(FFDIM/128,  MROWS/128);   // N=4096 GEMM: 32x32

    ln_kernel<<<MROWS, 256>>>(x, ln1g, ln1b, xn);
    gemm_kernel<EPI_BIAS><<<gD, 256>>>(xn, wq, bq, nullptr, q, MROWS, DMODEL, DMODEL);
    gemm_kernel<EPI_BIAS><<<gD, 256>>>(xn, wk, bk, nullptr, k, MROWS, DMODEL, DMODEL);
    gemm_kernel<EPI_BIAS><<<gD, 256>>>(xn, wv, bv, nullptr, v, MROWS, DMODEL, DMODEL);
    attn_kernel<<<dim3(SEQ/64, BATCH*NHEAD), 256, ATTN_SMEM>>>(q, k, v, at);
    gemm_kernel<EPI_RES><<<gD, 256>>>(at, wo, bo, xn, r1, MROWS, DMODEL, DMODEL);
    ln_kernel<<<MROWS, 256>>>(r1, ln2g, ln2b, y);
    gemm_kernel<EPI_GELU><<<gF, 256>>>(y, w1, b1, nullptr, h, MROWS, FFDIM, DMODEL);
    gemm_kernel<EPI_RES><<<gD, 256>>>(h, w2, b2, y, out, MROWS, DMODEL, FFDIM);
}

// round 4
// speedup vs baseline: 3.4375x; 1.6307x over previous
#include <cuda_runtime.h>
#include <cuda_bf16.h>
#include <math.h>
#include <stdint.h>

// Problem constants
#define BATCH 2
#define SEQ   2048
#define DMODEL 1024
#define NHEAD 16
#define HDIM  64
#define FFDIM 4096
#define MROWS (BATCH*SEQ)   // 4096
#define LN_EPS 1e-5f

// ---------------- scratch buffers ------------------------------------------
__device__ float g_xn [MROWS*DMODEL];
__device__ float g_q  [MROWS*DMODEL];
__device__ float g_k  [MROWS*DMODEL];
__device__ float g_v  [MROWS*DMODEL];
__device__ float g_r1 [MROWS*DMODEL];
__device__ float g_y  [MROWS*DMODEL];

__device__ __nv_bfloat16 g_xnh[MROWS*DMODEL], g_xnl[MROWS*DMODEL];
__device__ __nv_bfloat16 g_yh [MROWS*DMODEL], g_yl [MROWS*DMODEL];
__device__ __nv_bfloat16 g_ath[MROWS*DMODEL], g_atl[MROWS*DMODEL];
__device__ __nv_bfloat16 g_hh [MROWS*FFDIM],  g_hl [MROWS*FFDIM];

__device__ __nv_bfloat16 g_wqh[DMODEL*DMODEL], g_wql[DMODEL*DMODEL];
__device__ __nv_bfloat16 g_wkh[DMODEL*DMODEL], g_wkl[DMODEL*DMODEL];
__device__ __nv_bfloat16 g_wvh[DMODEL*DMODEL], g_wvl[DMODEL*DMODEL];
__device__ __nv_bfloat16 g_woh[DMODEL*DMODEL], g_wol[DMODEL*DMODEL];
__device__ __nv_bfloat16 g_w1h[FFDIM*DMODEL],  g_w1l[FFDIM*DMODEL];
__device__ __nv_bfloat16 g_w2h[DMODEL*FFDIM],  g_w2l[DMODEL*FFDIM];

// ---------------- helpers ---------------------------------------------------
__device__ __forceinline__ uint32_t smem_to_u32(const void* p) {
    uint32_t a;
    asm("{ .reg .u64 t; cvta.to.shared.u64 t, %1; cvt.u32.u64 %0, t; }"
        : "=r"(a) : "l"(p));
    return a;
}
__device__ __forceinline__ void cp16(uint32_t d, const void* s) {
    asm volatile("cp.async.cg.shared.global [%0], [%1], 16;" :: "r"(d), "l"(s) : "memory");
}
#define CP_COMMIT() asm volatile("cp.async.commit_group;" ::: "memory")
#define CP_WAIT0()  asm volatile("cp.async.wait_group 0;" ::: "memory")

__device__ __forceinline__ void ldsm4(uint32_t* r, uint32_t addr) {
    asm volatile("ldmatrix.sync.aligned.m8n8.x4.shared.b16 {%0,%1,%2,%3}, [%4];"
        : "=r"(r[0]), "=r"(r[1]), "=r"(r[2]), "=r"(r[3]) : "r"(addr));
}
__device__ __forceinline__ void mma16816(float* c, const uint32_t* a,
                                         uint32_t b0, uint32_t b1) {
    asm volatile("mma.sync.aligned.m16n8k16.row.col.f32.bf16.bf16.f32 "
        "{%0,%1,%2,%3}, {%4,%5,%6,%7}, {%8,%9}, {%0,%1,%2,%3};"
        : "+f"(c[0]), "+f"(c[1]), "+f"(c[2]), "+f"(c[3])
        : "r"(a[0]), "r"(a[1]), "r"(a[2]), "r"(a[3]), "r"(b0), "r"(b1));
}

__device__ __forceinline__ uint32_t pack_bf2(float a, float b) {
    __nv_bfloat162 t;
    t.x = __float2bfloat16_rn(a);
    t.y = __float2bfloat16_rn(b);
    uint32_t u;
    *reinterpret_cast<__nv_bfloat162*>(&u) = t;
    return u;
}
__device__ __forceinline__ float gelu_exact(float v) {
    return 0.5f * v * (1.0f + erff(v * 0.70710678118654752440f));
}

// ---------------- weight hi/lo split ----------------------------------------
__global__ __launch_bounds__(256)
void split_kernel(const float* __restrict__ s, __nv_bfloat16* __restrict__ hi,
                  __nv_bfloat16* __restrict__ lo, int n4)
{
    int i = blockIdx.x * blockDim.x + threadIdx.x;
    if (i >= n4) return;
    float4 v = reinterpret_cast<const float4*>(s)[i];
    float hx = __bfloat162float(__float2bfloat16_rn(v.x));
    float hy = __bfloat162float(__float2bfloat16_rn(v.y));
    float hz = __bfloat162float(__float2bfloat16_rn(v.z));
    float hw = __bfloat162float(__float2bfloat16_rn(v.w));
    uint2 hu, lu;
    hu.x = pack_bf2(v.x, v.y);           hu.y = pack_bf2(v.z, v.w);
    lu.x = pack_bf2(v.x - hx, v.y - hy); lu.y = pack_bf2(v.z - hz, v.w - hw);
    reinterpret_cast<uint2*>(hi)[i] = hu;
    reinterpret_cast<uint2*>(lo)[i] = lu;
}

// ---------------- LayerNorm + split ----------------------------------------
__global__ __launch_bounds__(256)
void ln_split_kernel(const float* __restrict__ x, const float* __restrict__ g,
                     const float* __restrict__ b, float* __restrict__ y,
                     __nv_bfloat16* __restrict__ yh, __nv_bfloat16* __restrict__ yl)
{
    int row = blockIdx.x;
    int tid = threadIdx.x;
    const float4* xr = reinterpret_cast<const float4*>(x + (size_t)row * DMODEL);
    float4 v = xr[tid];

    float s = v.x + v.y + v.z + v.w;
    float q = v.x*v.x + v.y*v.y + v.z*v.z + v.w*v.w;
    #pragma unroll
    for (int o = 16; o > 0; o >>= 1) {
        s += __shfl_down_sync(0xffffffffu, s, o);
        q += __shfl_down_sync(0xffffffffu, q, o);
    }
    __shared__ float ss[8], sq[8];
    int wid = tid >> 5, lane = tid & 31;
    if (lane == 0) { ss[wid] = s; sq[wid] = q; }
    __syncthreads();
    float tot = 0.f, totq = 0.f;
    #pragma unroll
    for (int i = 0; i < 8; ++i) { tot += ss[i]; totq += sq[i]; }

    float mu  = tot * (1.0f / DMODEL);
    float var = totq * (1.0f / DMODEL) - mu * mu;
    float rs  = rsqrtf(var + LN_EPS);

    float4 gg = reinterpret_cast<const float4*>(g)[tid];
    float4 bb = reinterpret_cast<const float4*>(b)[tid];
    float4 o;
    o.x = (v.x - mu) * rs * gg.x + bb.x;
    o.y = (v.y - mu) * rs * gg.y + bb.y;
    o.z = (v.z - mu) * rs * gg.z + bb.z;
    o.w = (v.w - mu) * rs * gg.w + bb.w;
    reinterpret_cast<float4*>(y + (size_t)row * DMODEL)[tid] = o;

    float hx = __bfloat162float(__float2bfloat16_rn(o.x));
    float hy = __bfloat162float(__float2bfloat16_rn(o.y));
    float hz = __bfloat162float(__float2bfloat16_rn(o.z));
    float hw = __bfloat162float(__float2bfloat16_rn(o.w));
    uint2 hu, lu;
    hu.x = pack_bf2(o.x, o.y);           hu.y = pack_bf2(o.z, o.w);
    lu.x = pack_bf2(o.x - hx, o.y - hy); lu.y = pack_bf2(o.z - hz, o.w - hw);
    reinterpret_cast<uint2*>(yh + (size_t)row * DMODEL)[tid] = hu;
    reinterpret_cast<uint2*>(yl + (size_t)row * DMODEL)[tid] = lu;
}

// ---------------- warp-MMA GEMM ---------------------------------------------
// C[M,N] = (Ah+Al)[M,K] @ (Wh+Wl)[N,K]^T via Ah*Wh + Al*Wh + Ah*Wl, fp32 acc.
// 128x128 CTA tile, BK=32, 8 warps (64x32 each), mma.sync m16n8k16 bf16.
#define EPI_QKV   0
#define EPI_RES   1
#define EPI_GELUS 2

#define GROWB  80                      // smem bytes per 32-col bf16 row
#define MATB   (128 * GROWB)           // 10240 per matrix tile
#define OFF_AH 0
#define OFF_AL MATB
#define OFF_WH (2*MATB)
#define OFF_WL (3*MATB)
#define STAGEB (4*MATB)                // 40960
#define GEMM_SMEM (2*STAGEB)           // 81920

template<int EPI>
__global__ __launch_bounds__(256, 1)
void gemm_mma(const __nv_bfloat16* __restrict__ Ah, const __nv_bfloat16* __restrict__ Al,
              const __nv_bfloat16* __restrict__ Wh, const __nv_bfloat16* __restrict__ Wl,
              const float* __restrict__ bias, const float* __restrict__ res,
              float* __restrict__ Cf, __nv_bfloat16* __restrict__ Chi,
              __nv_bfloat16* __restrict__ Clo, int M, int N, int K)
{
    extern __shared__ char smc[];
    uint32_t sb = smem_to_u32(smc);
    int tid  = threadIdx.x;
    int lane = tid & 31;
    int warp = tid >> 5;
    int n0 = blockIdx.x * 128;
    int m0 = blockIdx.y * 128;
    int wm = (warp >> 2) * 64;
    int wn = (warp & 3) * 32;

    // loader mapping: row r (0..127), half hf (0/1) -> 32 bytes at col hf*16 elems
    int r  = tid >> 1;
    int hf = tid & 1;
    const __nv_bfloat16* gAh = Ah + (size_t)(m0 + r) * K + hf * 16;
    const __nv_bfloat16* gAl = Al + (size_t)(m0 + r) * K + hf * 16;
    const __nv_bfloat16* gWh = Wh + (size_t)(n0 + r) * K + hf * 16;
    const __nv_bfloat16* gWl = Wl + (size_t)(n0 + r) * K + hf * 16;
    uint32_t sdst = sb + r * GROWB + hf * 32;

    float acc[4][4][4];
    #pragma unroll
    for (int mi = 0; mi < 4; ++mi)
        #pragma unroll
        for (int nj = 0; nj < 4; ++nj)
            #pragma unroll
            for (int e = 0; e < 4; ++e) acc[mi][nj][e] = 0.f;

    // ldmatrix address offset within a tile (shared by A and W patterns)
    uint32_t lmo = (uint32_t)((lane & 15) * GROWB + (lane >> 4) * 16);

    int nch = K / 32;

    // prologue: stage 0
    {
        cp16(sdst + OFF_AH, gAh);      cp16(sdst + OFF_AH + 16, gAh + 8);
        cp16(sdst + OFF_AL, gAl);      cp16(sdst + OFF_AL + 16, gAl + 8);
        cp16(sdst + OFF_WH, gWh);      cp16(sdst + OFF_WH + 16, gWh + 8);
        cp16(sdst + OFF_WL, gWl);      cp16(sdst + OFF_WL + 16, gWl + 8);
        CP_COMMIT();
        CP_WAIT0();
        __syncthreads();
    }

    for (int c = 0; c < nch; ++c) {
        int s = c & 1;
        if (c + 1 < nch) {
            size_t ko = (size_t)(c + 1) * 32;
            uint32_t d2 = sdst + (s ^ 1) * STAGEB;
            cp16(d2 + OFF_AH, gAh + ko);  cp16(d2 + OFF_AH + 16, gAh + ko + 8);
            cp16(d2 + OFF_AL, gAl + ko);  cp16(d2 + OFF_AL + 16, gAl + ko + 8);
            cp16(d2 + OFF_WH, gWh + ko);  cp16(d2 + OFF_WH + 16, gWh + ko + 8);
            cp16(d2 + OFF_WL, gWl + ko);  cp16(d2 + OFF_WL + 16, gWl + ko + 8);
            CP_COMMIT();
        }

        uint32_t stgb = sb + s * STAGEB;
        #pragma unroll
        for (int ks = 0; ks < 2; ++ks) {
            uint32_t kb = ks * 32;
            uint32_t aH[4][4], aL[4][4], bH[2][4], bL[2][4];
            #pragma unroll
            for (int mi = 0; mi < 4; ++mi) {
                uint32_t ra = (wm + mi * 16) * GROWB + lmo + kb;
                ldsm4(aH[mi], stgb + OFF_AH + ra);
                ldsm4(aL[mi], stgb + OFF_AL + ra);
            }
            #pragma unroll
            for (int p = 0; p < 2; ++p) {
                uint32_t rb = (wn + p * 16) * GROWB + lmo + kb;
                ldsm4(bH[p], stgb + OFF_WH + rb);
                ldsm4(bL[p], stgb + OFF_WL + rb);
            }
            #pragma unroll
            for (int mi = 0; mi < 4; ++mi) {
                #pragma unroll
                for (int nj = 0; nj < 4; ++nj) {
                    uint32_t bh0 = bH[nj >> 1][nj & 1];
                    uint32_t bh1 = bH[nj >> 1][(nj & 1) + 2];
                    uint32_t bl0 = bL[nj >> 1][nj & 1];
                    uint32_t bl1 = bL[nj >> 1][(nj & 1) + 2];
                    mma16816(acc[mi][nj], aH[mi], bh0, bh1);
                    mma16816(acc[mi][nj], aL[mi], bh0, bh1);
                    mma16816(acc[mi][nj], aH[mi], bl0, bl1);
                }
            }
        }

        if (c + 1 < nch) CP_WAIT0();
        __syncthreads();
    }

    // ---------------- epilogue ----------------
    int gid  = lane >> 2;
    int tid4 = lane & 3;
    float b2v[4][2];
    #pragma unroll
    for (int nj = 0; nj < 4; ++nj) {
        int col = n0 + wn + nj * 8 + tid4 * 2;
        b2v[nj][0] = bias[col];
        b2v[nj][1] = bias[col + 1];
    }
    #pragma unroll
    for (int mi = 0; mi < 4; ++mi) {
        #pragma unroll
        for (int half = 0; half < 2; ++half) {
            int row = m0 + wm + mi * 16 + gid + half * 8;
            #pragma unroll
            for (int nj = 0; nj < 4; ++nj) {
                int col = n0 + wn + nj * 8 + tid4 * 2;
                float v0 = acc[mi][nj][half * 2 + 0] + b2v[nj][0];
                float v1 = acc[mi][nj][half * 2 + 1] + b2v[nj][1];
                if (EPI == EPI_RES) {
                    float2 rv = *reinterpret_cast<const float2*>(&res[(size_t)row * N + col]);
                    v0 += rv.x; v1 += rv.y;
                }
                if (EPI == EPI_GELUS) {
                    v0 = gelu_exact(v0); v1 = gelu_exact(v1);
                    float h0 = __bfloat162float(__float2bfloat16_rn(v0));
                    float h1 = __bfloat162float(__float2bfloat16_rn(v1));
                    *reinterpret_cast<uint32_t*>(&Chi[(size_t)row * N + col]) = pack_bf2(v0, v1);
                    *reinterpret_cast<uint32_t*>(&Clo[(size_t)row * N + col]) = pack_bf2(v0 - h0, v1 - h1);
                } else {
                    float2 o; o.x = v0; o.y = v1;
                    *reinterpret_cast<float2*>(&Cf[(size_t)row * N + col]) = o;
                }
            }
        }
    }
}

// ---------------- Flash attention (2 query rows / thread) -------------------
#define AST 68
#define ATTN_SMEM ((128 + 64 + 64 + 128) * AST * 4)

__global__ __launch_bounds__(256)
void attn_kernel(const float* __restrict__ Q, const float* __restrict__ K,
                 const float* __restrict__ V,
                 __nv_bfloat16* __restrict__ Ohi, __nv_bfloat16* __restrict__ Olo)
{
    extern __shared__ float sm[];
    float* Qs = sm;                       // 128 rows
    float* Ks = Qs + 128 * AST;           // 64 rows
    float* Vs = Ks + 64 * AST;            // 64 rows
    float* Ps = Vs + 64 * AST;            // 128 rows x 64 keys

    int tid = threadIdx.x;
    int bh = blockIdx.y;
    int b = bh >> 4, h = bh & 15;
    int qbase  = b * SEQ + blockIdx.x * 128;
    int kvbase = b * SEQ;
    int hcol   = h * HDIM;

    #pragma unroll 2
    for (int i = tid; i < 128 * 16; i += 256) {
        int row = i >> 4, cc = i & 15;
        float4 tq = *reinterpret_cast<const float4*>(
            &Q[(size_t)(qbase + row) * DMODEL + hcol + cc*4]);
        *reinterpret_cast<float4*>(&Qs[row * AST + cc*4]) = tq;
    }

    int r = tid >> 2;
    int g = tid & 3;

    float m0v = -1e30f, l0v = 0.f, m1v = -1e30f, l1v = 0.f;
    float acc0[16], acc1[16];
    #pragma unroll
    for (int d = 0; d < 16; ++d) { acc0[d] = 0.f; acc1[d] = 0.f; }

    const float scale = 0.125f;

    for (int t = 0; t < SEQ / 64; ++t) {
        __syncthreads();
        #pragma unroll 2
        for (int i = tid; i < 64 * 16; i += 256) {
            int row = i >> 4, cc = i & 15;
            size_t gidx = (size_t)(kvbase + t*64 + row) * DMODEL + hcol + cc*4;
            *reinterpret_cast<float4*>(&Ks[row * AST + cc*4]) =
                *reinterpret_cast<const float4*>(&K[gidx]);
            *reinterpret_cast<float4*>(&Vs[row * AST + cc*4]) =
                *reinterpret_cast<const float4*>(&V[gidx]);
        }
        __syncthreads();

        float s0[16], s1[16];
        #pragma unroll
        for (int j = 0; j < 16; ++j) { s0[j] = 0.f; s1[j] = 0.f; }
        #pragma unroll
        for (int dc = 0; dc < 16; ++dc) {
            float4 q0 = *reinterpret_cast<float4*>(&Qs[r * AST + dc*4]);
            float4 q1 = *reinterpret_cast<float4*>(&Qs[(r + 64) * AST + dc*4]);
            #pragma unroll
            for (int j = 0; j < 16; ++j) {
                float4 k4 = *reinterpret_cast<float4*>(&Ks[(4*j + g) * AST + dc*4]);
                s0[j] += q0.x*k4.x + q0.y*k4.y + q0.z*k4.z + q0.w*k4.w;
                s1[j] += q1.x*k4.x + q1.y*k4.y + q1.z*k4.z + q1.w*k4.w;
            }
        }

        float mn = m0v;
        #pragma unroll
        for (int j = 0; j < 16; ++j) { s0[j] *= scale; mn = fmaxf(mn, s0[j]); }
        mn = fmaxf(mn, __shfl_xor_sync(0xffffffffu, mn, 1));
        mn = fmaxf(mn, __shfl_xor_sync(0xffffffffu, mn, 2));
        float a0 = __expf(m0v - mn);
        float ls = 0.f;
        #pragma unroll
        for (int j = 0; j < 16; ++j) { s0[j] = __expf(s0[j] - mn); ls += s0[j]; }
        ls += __shfl_xor_sync(0xffffffffu, ls, 1);
        ls += __shfl_xor_sync(0xffffffffu, ls, 2);
        l0v = l0v * a0 + ls; m0v = mn;

        mn = m1v;
        #pragma unroll
        for (int j = 0; j < 16; ++j) { s1[j] *= scale; mn = fmaxf(mn, s1[j]); }
        mn = fmaxf(mn, __shfl_xor_sync(0xffffffffu, mn, 1));
        mn = fmaxf(mn, __shfl_xor_sync(0xffffffffu, mn, 2));
        float a1 = __expf(m1v - mn);
        ls = 0.f;
        #pragma unroll
        for (int j = 0; j < 16; ++j) { s1[j] = __expf(s1[j] - mn); ls += s1[j]; }
        ls += __shfl_xor_sync(0xffffffffu, ls, 1);
        ls += __shfl_xor_sync(0xffffffffu, ls, 2);
        l1v = l1v * a1 + ls; m1v = mn;

        #pragma unroll
        for (int j = 0; j < 16; ++j) {
            Ps[r * AST + 4*j + g]        = s0[j];
            Ps[(r + 64) * AST + 4*j + g] = s1[j];
        }
        #pragma unroll
        for (int d = 0; d < 16; ++d) { acc0[d] *= a0; acc1[d] *= a1; }
        __syncwarp();

        #pragma unroll
        for (int kk = 0; kk < 64; ++kk) {
            float p0 = Ps[r * AST + kk];
            float p1 = Ps[(r + 64) * AST + kk];
            const float* vr = &Vs[kk * AST + g*16];
            float4 v0 = *reinterpret_cast<const float4*>(vr);
            float4 v1 = *reinterpret_cast<const float4*>(vr + 4);
            float4 v2 = *reinterpret_cast<const float4*>(vr + 8);
            float4 v3 = *reinterpret_cast<const float4*>(vr + 12);
            acc0[0]  += p0*v0.x; acc0[1]  += p0*v0.y; acc0[2]  += p0*v0.z; acc0[3]  += p0*v0.w;
            acc0[4]  += p0*v1.x; acc0[5]  += p0*v1.y; acc0[6]  += p0*v1.z; acc0[7]  += p0*v1.w;
            acc0[8]  += p0*v2.x; acc0[9]  += p0*v2.y; acc0[10] += p0*v2.z; acc0[11] += p0*v2.w;
            acc0[12] += p0*v3.x; acc0[13] += p0*v3.y; acc0[14] += p0*v3.z; acc0[15] += p0*v3.w;
            acc1[0]  += p1*v0.x; acc1[1]  += p1*v0.y; acc1[2]  += p1*v0.z; acc1[3]  += p1*v0.w;
            acc1[4]  += p1*v1.x; acc1[5]  += p1*v1.y; acc1[6]  += p1*v1.z; acc1[7]  += p1*v1.w;
            acc1[8]  += p1*v2.x; acc1[9]  += p1*v2.y; acc1[10] += p1*v2.z; acc1[11] += p1*v2.w;
            acc1[12] += p1*v3.x; acc1[13] += p1*v3.y; acc1[14] += p1*v3.z; acc1[15] += p1*v3.w;
        }
    }

    float il0 = 1.0f / l0v, il1 = 1.0f / l1v;
    #pragma unroll
    for (int rr = 0; rr < 2; ++rr) {
        float il = rr ? il1 : il0;
        float* acc = rr ? acc1 : acc0;
        int grow = qbase + r + rr * 64;
        uint32_t hu[8], lu[8];
        #pragma unroll
        for (int p = 0; p < 8; ++p) {
            float a = acc[2*p] * il, b2 = acc[2*p+1] * il;
            float ha = __bfloat162float(__float2bfloat16_rn(a));
            float hb = __bfloat162float(__float2bfloat16_rn(b2));
            hu[p] = pack_bf2(a, b2);
            lu[p] = pack_bf2(a - ha, b2 - hb);
        }
        uint4* hp = reinterpret_cast<uint4*>(&Ohi[(size_t)grow * DMODEL + hcol + g*16]);
        uint4* lp = reinterpret_cast<uint4*>(&Olo[(size_t)grow * DMODEL + hcol + g*16]);
        hp[0] = make_uint4(hu[0], hu[1], hu[2], hu[3]);
        hp[1] = make_uint4(hu[4], hu[5], hu[6], hu[7]);
        lp[0] = make_uint4(lu[0], lu[1], lu[2], lu[3]);
        lp[1] = make_uint4(lu[4], lu[5], lu[6], lu[7]);
    }
}

// ---------------- launch ----------------------------------------------------
extern "C" void kernel_launch(void* const* d_in, const int* in_sizes, int n_in,
                              void* d_out, int out_size)
{
    (void)in_sizes; (void)n_in; (void)out_size;
    const float* x    = (const float*)d_in[0];
    const float* wq   = (const float*)d_in[1];
    const float* bq   = (const float*)d_in[2];
    const float* wk   = (const float*)d_in[3];
    const float* bk   = (const float*)d_in[4];
    const float* wv   = (const float*)d_in[5];
    const float* bv   = (const float*)d_in[6];
    const float* wo   = (const float*)d_in[7];
    const float* bo   = (const float*)d_in[8];
    const float* ln1g = (const float*)d_in[9];
    const float* ln1b = (const float*)d_in[10];
    const float* w1   = (const float*)d_in[11];
    const float* b1   = (const float*)d_in[12];
    const float* w2   = (const float*)d_in[13];
    const float* b2   = (const float*)d_in[14];
    const float* ln2g = (const float*)d_in[15];
    const float* ln2b = (const float*)d_in[16];
    float* out = (float*)d_out;

    float *xn, *q, *k, *v, *r1, *y;
    cudaGetSymbolAddress((void**)&xn, g_xn);
    cudaGetSymbolAddress((void**)&q,  g_q);
    cudaGetSymbolAddress((void**)&k,  g_k);
    cudaGetSymbolAddress((void**)&v,  g_v);
    cudaGetSymbolAddress((void**)&r1, g_r1);
    cudaGetSymbolAddress((void**)&y,  g_y);

    __nv_bfloat16 *xnh,*xnl,*yh,*yl,*ath,*atl,*hh,*hl;
    __nv_bfloat16 *wqh,*wql,*wkh,*wkl,*wvh,*wvl,*woh,*wol,*w1h,*w1l,*w2h,*w2l;
    cudaGetSymbolAddress((void**)&xnh, g_xnh); cudaGetSymbolAddress((void**)&xnl, g_xnl);
    cudaGetSymbolAddress((void**)&yh,  g_yh);  cudaGetSymbolAddress((void**)&yl,  g_yl);
    cudaGetSymbolAddress((void**)&ath, g_ath); cudaGetSymbolAddress((void**)&atl, g_atl);
    cudaGetSymbolAddress((void**)&hh,  g_hh);  cudaGetSymbolAddress((void**)&hl,  g_hl);
    cudaGetSymbolAddress((void**)&wqh, g_wqh); cudaGetSymbolAddress((void**)&wql, g_wql);
    cudaGetSymbolAddress((void**)&wkh, g_wkh); cudaGetSymbolAddress((void**)&wkl, g_wkl);
    cudaGetSymbolAddress((void**)&wvh, g_wvh); cudaGetSymbolAddress((void**)&wvl, g_wvl);
    cudaGetSymbolAddress((void**)&woh, g_woh); cudaGetSymbolAddress((void**)&wol, g_wol);
    cudaGetSymbolAddress((void**)&w1h, g_w1h); cudaGetSymbolAddress((void**)&w1l, g_w1l);
    cudaGetSymbolAddress((void**)&w2h, g_w2h); cudaGetSymbolAddress((void**)&w2l, g_w2l);

    cudaFuncSetAttribute(attn_kernel, cudaFuncAttributeMaxDynamicSharedMemorySize, ATTN_SMEM);
    cudaFuncSetAttribute(gemm_mma<EPI_QKV>,   cudaFuncAttributeMaxDynamicSharedMemorySize, GEMM_SMEM);
    cudaFuncSetAttribute(gemm_mma<EPI_RES>,   cudaFuncAttributeMaxDynamicSharedMemorySize, GEMM_SMEM);
    cudaFuncSetAttribute(gemm_mma<EPI_GELUS>, cudaFuncAttributeMaxDynamicSharedMemorySize, GEMM_SMEM);

    int nDD4 = DMODEL*DMODEL/4, nFD4 = FFDIM*DMODEL/4;
    split_kernel<<<(nDD4+255)/256, 256>>>(wq, wqh, wql, nDD4);
    split_kernel<<<(nDD4+255)/256, 256>>>(wk, wkh, wkl, nDD4);
    split_kernel<<<(nDD4+255)/256, 256>>>(wv, wvh, wvl, nDD4);
    split_kernel<<<(nDD4+255)/256, 256>>>(wo, woh, wol, nDD4);
    split_kernel<<<(nFD4+255)/256, 256>>>(w1, w1h, w1l, nFD4);
    split_kernel<<<(nFD4+255)/256, 256>>>(w2, w2h, w2l, nFD4);

    dim3 gD(DMODEL/128, MROWS/128);   // 8 x 32
    dim3 gF(FFDIM/128,  MROWS/128);   // 32 x 32

    ln_split_kernel<<<MROWS, 256>>>(x, ln1g, ln1b, xn, xnh, xnl);
    gemm_mma<EPI_QKV><<<gD, 256, GEMM_SMEM>>>(xnh, xnl, wqh, wql, bq, nullptr, q, nullptr, nullptr, MROWS, DMODEL, DMODEL);
    gemm_mma<EPI_QKV><<<gD, 256, GEMM_SMEM>>>(xnh, xnl, wkh, wkl, bk, nullptr, k, nullptr, nullptr, MROWS, DMODEL, DMODEL);
    gemm_mma<EPI_QKV><<<gD, 256, GEMM_SMEM>>>(xnh, xnl, wvh, wvl, bv, nullptr, v, nullptr, nullptr, MROWS, DMODEL, DMODEL);
    attn_kernel<<<dim3(SEQ/128, BATCH*NHEAD), 256, ATTN_SMEM>>>(q, k, v, ath, atl);
    gemm_mma<EPI_RES><<<gD, 256, GEMM_SMEM>>>(ath, atl, woh, wol, bo, xn, r1, nullptr, nullptr, MROWS, DMODEL, DMODEL);
    ln_split_kernel<<<MROWS, 256>>>(r1, ln2g, ln2b, y, yh, yl);
    gemm_mma<EPI_GELUS><<<gF, 256, GEMM_SMEM>>>(yh, yl, w1h, w1l, b1, nullptr, nullptr, hh, hl, MROWS, FFDIM, DMODEL);
    gemm_mma<EPI_RES><<<gD, 256, GEMM_SMEM>>>(hh, hl, w2h, w2l, b2, y, out, nullptr, nullptr, MROWS, DMODEL, FFDIM);
}

// round 6
// speedup vs baseline: 6.0402x; 1.7572x over previous
#include <cuda_runtime.h>
#include <cuda_bf16.h>
#include <math.h>
#include <stdint.h>

// Problem constants
#define BATCH 2
#define SEQ   2048
#define DMODEL 1024
#define NHEAD 16
#define HDIM  64
#define FFDIM 4096
#define MROWS (BATCH*SEQ)   // 4096
#define LN_EPS 1e-5f

// ---------------- scratch buffers ------------------------------------------
__device__ float g_xn [MROWS*DMODEL];
__device__ float g_r1 [MROWS*DMODEL];
__device__ float g_y  [MROWS*DMODEL];

__device__ __nv_bfloat16 g_xnh[MROWS*DMODEL], g_xnl[MROWS*DMODEL];
__device__ __nv_bfloat16 g_yh [MROWS*DMODEL], g_yl [MROWS*DMODEL];
__device__ __nv_bfloat16 g_qh [MROWS*DMODEL], g_ql [MROWS*DMODEL];
__device__ __nv_bfloat16 g_kh [MROWS*DMODEL], g_kl [MROWS*DMODEL];
__device__ __nv_bfloat16 g_vh [MROWS*DMODEL], g_vl [MROWS*DMODEL];
__device__ __nv_bfloat16 g_ath[MROWS*DMODEL], g_atl[MROWS*DMODEL];
__device__ __nv_bfloat16 g_hh [MROWS*FFDIM],  g_hl [MROWS*FFDIM];

__device__ __nv_bfloat16 g_wqh[DMODEL*DMODEL], g_wql[DMODEL*DMODEL];
__device__ __nv_bfloat16 g_wkh[DMODEL*DMODEL], g_wkl[DMODEL*DMODEL];
__device__ __nv_bfloat16 g_wvh[DMODEL*DMODEL], g_wvl[DMODEL*DMODEL];
__device__ __nv_bfloat16 g_woh[DMODEL*DMODEL], g_wol[DMODEL*DMODEL];
__device__ __nv_bfloat16 g_w1h[FFDIM*DMODEL],  g_w1l[FFDIM*DMODEL];
__device__ __nv_bfloat16 g_w2h[DMODEL*FFDIM],  g_w2l[DMODEL*FFDIM];

// ---------------- helpers ---------------------------------------------------
__device__ __forceinline__ uint32_t smem_to_u32(const void* p) {
    uint32_t a;
    asm("{ .reg .u64 t; cvta.to.shared.u64 t, %1; cvt.u32.u64 %0, t; }"
        : "=r"(a) : "l"(p));
    return a;
}
__device__ __forceinline__ void cp16(uint32_t d, const void* s) {
    asm volatile("cp.async.cg.shared.global [%0], [%1], 16;" :: "r"(d), "l"(s) : "memory");
}
#define CP_COMMIT() asm volatile("cp.async.commit_group;" ::: "memory")
#define CP_WAIT0()  asm volatile("cp.async.wait_group 0;" ::: "memory")

__device__ __forceinline__ void ldsm4(uint32_t* r, uint32_t addr) {
    asm volatile("ldmatrix.sync.aligned.m8n8.x4.shared.b16 {%0,%1,%2,%3}, [%4];"
        : "=r"(r[0]), "=r"(r[1]), "=r"(r[2]), "=r"(r[3]) : "r"(addr));
}
__device__ __forceinline__ void ldsm4t(uint32_t* r, uint32_t addr) {
    asm volatile("ldmatrix.sync.aligned.m8n8.x4.trans.shared.b16 {%0,%1,%2,%3}, [%4];"
        : "=r"(r[0]), "=r"(r[1]), "=r"(r[2]), "=r"(r[3]) : "r"(addr));
}
__device__ __forceinline__ void mma16816(float* c, const uint32_t* a,
                                         uint32_t b0, uint32_t b1) {
    asm volatile("mma.sync.aligned.m16n8k16.row.col.f32.bf16.bf16.f32 "
        "{%0,%1,%2,%3}, {%4,%5,%6,%7}, {%8,%9}, {%0,%1,%2,%3};"
        : "+f"(c[0]), "+f"(c[1]), "+f"(c[2]), "+f"(c[3])
        : "r"(a[0]), "r"(a[1]), "r"(a[2]), "r"(a[3]), "r"(b0), "r"(b1));
}

__device__ __forceinline__ uint32_t pack_bf2(float a, float b) {
    __nv_bfloat162 t;
    t.x = __float2bfloat16_rn(a);
    t.y = __float2bfloat16_rn(b);
    uint32_t u;
    *reinterpret_cast<__nv_bfloat162*>(&u) = t;
    return u;
}
__device__ __forceinline__ float bf_hi(float v) {
    return __bfloat162float(__float2bfloat16_rn(v));
}
__device__ __forceinline__ float gelu_exact(float v) {
    return 0.5f * v * (1.0f + erff(v * 0.70710678118654752440f));
}

// ---------------- weight hi/lo split ----------------------------------------
__global__ __launch_bounds__(256)
void split_kernel(const float* __restrict__ s, __nv_bfloat16* __restrict__ hi,
                  __nv_bfloat16* __restrict__ lo, int n4)
{
    int i = blockIdx.x * blockDim.x + threadIdx.x;
    if (i >= n4) return;
    float4 v = reinterpret_cast<const float4*>(s)[i];
    uint2 hu, lu;
    hu.x = pack_bf2(v.x, v.y);
    hu.y = pack_bf2(v.z, v.w);
    lu.x = pack_bf2(v.x - bf_hi(v.x), v.y - bf_hi(v.y));
    lu.y = pack_bf2(v.z - bf_hi(v.z), v.w - bf_hi(v.w));
    reinterpret_cast<uint2*>(hi)[i] = hu;
    reinterpret_cast<uint2*>(lo)[i] = lu;
}

// ---------------- LayerNorm + split ----------------------------------------
__global__ __launch_bounds__(256)
void ln_split_kernel(const float* __restrict__ x, const float* __restrict__ g,
                     const float* __restrict__ b, float* __restrict__ y,
                     __nv_bfloat16* __restrict__ yh, __nv_bfloat16* __restrict__ yl)
{
    int row = blockIdx.x;
    int tid = threadIdx.x;
    const float4* xr = reinterpret_cast<const float4*>(x + (size_t)row * DMODEL);
    float4 v = xr[tid];

    float s = v.x + v.y + v.z + v.w;
    float q = v.x*v.x + v.y*v.y + v.z*v.z + v.w*v.w;
    #pragma unroll
    for (int o = 16; o > 0; o >>= 1) {
        s += __shfl_down_sync(0xffffffffu, s, o);
        q += __shfl_down_sync(0xffffffffu, q, o);
    }
    __shared__ float ss[8], sq[8];
    int wid = tid >> 5, lane = tid & 31;
    if (lane == 0) { ss[wid] = s; sq[wid] = q; }
    __syncthreads();
    float tot = 0.f, totq = 0.f;
    #pragma unroll
    for (int i = 0; i < 8; ++i) { tot += ss[i]; totq += sq[i]; }

    float mu  = tot * (1.0f / DMODEL);
    float var = totq * (1.0f / DMODEL) - mu * mu;
    float rs  = rsqrtf(var + LN_EPS);

    float4 gg = reinterpret_cast<const float4*>(g)[tid];
    float4 bb = reinterpret_cast<const float4*>(b)[tid];
    float4 o;
    o.x = (v.x - mu) * rs * gg.x + bb.x;
    o.y = (v.y - mu) * rs * gg.y + bb.y;
    o.z = (v.z - mu) * rs * gg.z + bb.z;
    o.w = (v.w - mu) * rs * gg.w + bb.w;
    reinterpret_cast<float4*>(y + (size_t)row * DMODEL)[tid] = o;

    uint2 hu, lu;
    hu.x = pack_bf2(o.x, o.y);
    hu.y = pack_bf2(o.z, o.w);
    lu.x = pack_bf2(o.x - bf_hi(o.x), o.y - bf_hi(o.y));
    lu.y = pack_bf2(o.z - bf_hi(o.z), o.w - bf_hi(o.w));
    reinterpret_cast<uint2*>(yh + (size_t)row * DMODEL)[tid] = hu;
    reinterpret_cast<uint2*>(yl + (size_t)row * DMODEL)[tid] = lu;
}

// ---------------- warp-MMA GEMM ---------------------------------------------
#define EPI_RES   1
#define EPI_GELUS 2
#define EPI_SPLIT 3

#define GROWB  80
#define MATB   (128 * GROWB)
#define OFF_AH 0
#define OFF_AL MATB
#define OFF_WH (2*MATB)
#define OFF_WL (3*MATB)
#define STAGEB (4*MATB)
#define GEMM_SMEM (2*STAGEB)

template<int EPI>
__global__ __launch_bounds__(256, 1)
void gemm_mma(const __nv_bfloat16* __restrict__ Ah, const __nv_bfloat16* __restrict__ Al,
              const __nv_bfloat16* __restrict__ Wh, const __nv_bfloat16* __restrict__ Wl,
              const float* __restrict__ bias, const float* __restrict__ res,
              float* __restrict__ Cf, __nv_bfloat16* __restrict__ Chi,
              __nv_bfloat16* __restrict__ Clo, int M, int N, int K)
{
    extern __shared__ char smc[];
    uint32_t sb = smem_to_u32(smc);
    int tid  = threadIdx.x;
    int lane = tid & 31;
    int warp = tid >> 5;
    int n0 = blockIdx.x * 128;
    int m0 = blockIdx.y * 128;
    int wm = (warp >> 2) * 64;
    int wn = (warp & 3) * 32;

    int r  = tid >> 1;
    int hf = tid & 1;
    const __nv_bfloat16* gAh = Ah + (size_t)(m0 + r) * K + hf * 16;
    const __nv_bfloat16* gAl = Al + (size_t)(m0 + r) * K + hf * 16;
    const __nv_bfloat16* gWh = Wh + (size_t)(n0 + r) * K + hf * 16;
    const __nv_bfloat16* gWl = Wl + (size_t)(n0 + r) * K + hf * 16;
    uint32_t sdst = sb + r * GROWB + hf * 32;

    float acc[4][4][4];
    #pragma unroll
    for (int mi = 0; mi < 4; ++mi)
        #pragma unroll
        for (int nj = 0; nj < 4; ++nj)
            #pragma unroll
            for (int e = 0; e < 4; ++e) acc[mi][nj][e] = 0.f;

    uint32_t lmo = (uint32_t)((lane & 15) * GROWB + (lane >> 4) * 16);
    int nch = K / 32;

    {
        cp16(sdst + OFF_AH, gAh);      cp16(sdst + OFF_AH + 16, gAh + 8);
        cp16(sdst + OFF_AL, gAl);      cp16(sdst + OFF_AL + 16, gAl + 8);
        cp16(sdst + OFF_WH, gWh);      cp16(sdst + OFF_WH + 16, gWh + 8);
        cp16(sdst + OFF_WL, gWl);      cp16(sdst + OFF_WL + 16, gWl + 8);
        CP_COMMIT();
        CP_WAIT0();
        __syncthreads();
    }

    for (int c = 0; c < nch; ++c) {
        int s = c & 1;
        if (c + 1 < nch) {
            size_t ko = (size_t)(c + 1) * 32;
            uint32_t d2 = sdst + (s ^ 1) * STAGEB;
            cp16(d2 + OFF_AH, gAh + ko);  cp16(d2 + OFF_AH + 16, gAh + ko + 8);
            cp16(d2 + OFF_AL, gAl + ko);  cp16(d2 + OFF_AL + 16, gAl + ko + 8);
            cp16(d2 + OFF_WH, gWh + ko);  cp16(d2 + OFF_WH + 16, gWh + ko + 8);
            cp16(d2 + OFF_WL, gWl + ko);  cp16(d2 + OFF_WL + 16, gWl + ko + 8);
            CP_COMMIT();
        }

        uint32_t stgb = sb + s * STAGEB;
        #pragma unroll
        for (int ks = 0; ks < 2; ++ks) {
            uint32_t kb = ks * 32;
            uint32_t aH[4][4], aL[4][4], bH[2][4], bL[2][4];
            #pragma unroll
            for (int mi = 0; mi < 4; ++mi) {
                uint32_t ra = (wm + mi * 16) * GROWB + lmo + kb;
                ldsm4(aH[mi], stgb + OFF_AH + ra);
                ldsm4(aL[mi], stgb + OFF_AL + ra);
            }
            #pragma unroll
            for (int p = 0; p < 2; ++p) {
                uint32_t rb = (wn + p * 16) * GROWB + lmo + kb;
                ldsm4(bH[p], stgb + OFF_WH + rb);
                ldsm4(bL[p], stgb + OFF_WL + rb);
            }
            #pragma unroll
            for (int mi = 0; mi < 4; ++mi) {
                #pragma unroll
                for (int nj = 0; nj < 4; ++nj) {
                    uint32_t bh0 = bH[nj >> 1][nj & 1];
                    uint32_t bh1 = bH[nj >> 1][(nj & 1) + 2];
                    uint32_t bl0 = bL[nj >> 1][nj & 1];
                    uint32_t bl1 = bL[nj >> 1][(nj & 1) + 2];
                    mma16816(acc[mi][nj], aH[mi], bh0, bh1);
                    mma16816(acc[mi][nj], aL[mi], bh0, bh1);
                    mma16816(acc[mi][nj], aH[mi], bl0, bl1);
                }
            }
        }

        if (c + 1 < nch) CP_WAIT0();
        __syncthreads();
    }

    int gid  = lane >> 2;
    int tid4 = lane & 3;
    float b2v[4][2];
    #pragma unroll
    for (int nj = 0; nj < 4; ++nj) {
        int col = n0 + wn + nj * 8 + tid4 * 2;
        b2v[nj][0] = bias[col];
        b2v[nj][1] = bias[col + 1];
    }
    #pragma unroll
    for (int mi = 0; mi < 4; ++mi) {
        #pragma unroll
        for (int half = 0; half < 2; ++half) {
            int row = m0 + wm + mi * 16 + gid + half * 8;
            #pragma unroll
            for (int nj = 0; nj < 4; ++nj) {
                int col = n0 + wn + nj * 8 + tid4 * 2;
                float v0 = acc[mi][nj][half * 2 + 0] + b2v[nj][0];
                float v1 = acc[mi][nj][half * 2 + 1] + b2v[nj][1];
                if (EPI == EPI_RES) {
                    float2 rv = *reinterpret_cast<const float2*>(&res[(size_t)row * N + col]);
                    v0 += rv.x; v1 += rv.y;
                    float2 o; o.x = v0; o.y = v1;
                    *reinterpret_cast<float2*>(&Cf[(size_t)row * N + col]) = o;
                } else {
                    if (EPI == EPI_GELUS) { v0 = gelu_exact(v0); v1 = gelu_exact(v1); }
                    *reinterpret_cast<uint32_t*>(&Chi[(size_t)row * N + col]) = pack_bf2(v0, v1);
                    *reinterpret_cast<uint32_t*>(&Clo[(size_t)row * N + col]) =
                        pack_bf2(v0 - bf_hi(v0), v1 - bf_hi(v1));
                }
            }
        }
    }
}

// ---------------- MMA flash attention ---------------------------------------
// grid = (SEQ/128, B*H), 256 threads (8 warps, 16 query rows each).
// K tiles of 64 keys, double-buffered cp.async. hi/lo bf16 compensation on
// both QK^T and PV (3 mma each).
#define QST 72                         // smem row stride in bf16 elems (144B)
#define AQH 0
#define AQL (128*QST)
#define AKV0 (2*128*QST)               // stage base
#define KVSTG (4*64*QST)               // elems per stage (Kh,Kl,Vh,Vl)
#define AOF_KH 0
#define AOF_KL (64*QST)
#define AOF_VH (2*64*QST)
#define AOF_VL (3*64*QST)
#define ATTN_SMEM ((2*128*QST + 2*KVSTG) * 2)   // bytes

__global__ __launch_bounds__(256, 1)
void attn_mma(const __nv_bfloat16* __restrict__ Qh, const __nv_bfloat16* __restrict__ Ql,
              const __nv_bfloat16* __restrict__ Kh, const __nv_bfloat16* __restrict__ Kl,
              const __nv_bfloat16* __restrict__ Vh, const __nv_bfloat16* __restrict__ Vl,
              __nv_bfloat16* __restrict__ Ohi, __nv_bfloat16* __restrict__ Olo)
{
    extern __shared__ __nv_bfloat16 sma[];
    uint32_t sb = smem_to_u32(sma);

    int tid  = threadIdx.x;
    int lane = tid & 31;
    int warp = tid >> 5;
    int bh = blockIdx.y;
    int b = bh >> 4, h = bh & 15;
    int qbase  = b * SEQ + blockIdx.x * 128;
    int kvbase = b * SEQ;
    int hcol   = h * HDIM;
    int wm = warp * 16;

    // ---- load Q (128 rows x 64 cols, hi+lo): 2 threads per row ----
    {
        int rr = tid >> 1, cc2 = (tid & 1) * 4;
        const __nv_bfloat16* gq = Qh + (size_t)(qbase + rr) * DMODEL + hcol + cc2 * 8;
        const __nv_bfloat16* gl = Ql + (size_t)(qbase + rr) * DMODEL + hcol + cc2 * 8;
        uint32_t dq = sb + (rr * QST + cc2 * 8) * 2;
        #pragma unroll
        for (int c = 0; c < 4; ++c) {
            cp16(dq + AQH * 2 + c * 16, gq + c * 8);
            cp16(dq + AQL * 2 + c * 16, gl + c * 8);
        }
    }

    // ---- KV stage loader: 4 threads per row (64 rows per tile) ----
    int krr = tid >> 2;              // 0..63
    int kc4 = (tid & 3) * 16;        // elem offset within 64-col row
    uint32_t kdst = sb + (krr * QST + kc4) * 2;
    size_t kgo = (size_t)hcol + kc4;

    {   // prologue stage 0 (tile 0)
        size_t grow = (size_t)(kvbase + krr) * DMODEL + kgo;
        uint32_t st = kdst + AKV0 * 2;
        cp16(st + AOF_KH*2,      Kh + grow);  cp16(st + AOF_KH*2 + 16, Kh + grow + 8);
        cp16(st + AOF_KL*2,      Kl + grow);  cp16(st + AOF_KL*2 + 16, Kl + grow + 8);
        cp16(st + AOF_VH*2,      Vh + grow);  cp16(st + AOF_VH*2 + 16, Vh + grow + 8);
        cp16(st + AOF_VL*2,      Vl + grow);  cp16(st + AOF_VL*2 + 16, Vl + grow + 8);
        CP_COMMIT();
        CP_WAIT0();
        __syncthreads();
    }

    float oacc[8][4];
    #pragma unroll
    for (int j = 0; j < 8; ++j)
        #pragma unroll
        for (int e = 0; e < 4; ++e) oacc[j][e] = 0.f;
    float mrow[2] = {-1e30f, -1e30f};
    float lrow[2] = {0.f, 0.f};

    uint32_t lmo = (uint32_t)((lane & 15) * QST * 2 + (lane >> 4) * 16);
    const float scale = 0.125f;

    const int NT = SEQ / 64;
    for (int t = 0; t < NT; ++t) {
        int s = t & 1;
        if (t + 1 < NT) {
            size_t grow = (size_t)(kvbase + (t + 1) * 64 + krr) * DMODEL + kgo;
            uint32_t st = kdst + (AKV0 + (s ^ 1) * KVSTG) * 2;
            cp16(st + AOF_KH*2,      Kh + grow);  cp16(st + AOF_KH*2 + 16, Kh + grow + 8);
            cp16(st + AOF_KL*2,      Kl + grow);  cp16(st + AOF_KL*2 + 16, Kl + grow + 8);
            cp16(st + AOF_VH*2,      Vh + grow);  cp16(st + AOF_VH*2 + 16, Vh + grow + 8);
            cp16(st + AOF_VL*2,      Vl + grow);  cp16(st + AOF_VL*2 + 16, Vl + grow + 8);
            CP_COMMIT();
        }

        uint32_t kvb = sb + (AKV0 + s * KVSTG) * 2;

        // ---- scores: S[16 x 64] = Q_tile . K_tile^T ----
        float sacc[8][4];
        #pragma unroll
        for (int j = 0; j < 8; ++j)
            #pragma unroll
            for (int e = 0; e < 4; ++e) sacc[j][e] = 0.f;

        #pragma unroll
        for (int kk = 0; kk < 4; ++kk) {
            uint32_t aH[4], aL[4], bH[4], bL[4];
            uint32_t qa = sb + wm * QST * 2 + lmo + kk * 32;
            ldsm4(aH, qa + AQH * 2);
            ldsm4(aL, qa + AQL * 2);
            #pragma unroll
            for (int p = 0; p < 4; ++p) {
                uint32_t ka = kvb + p * 16 * QST * 2 + lmo + kk * 32;
                ldsm4(bH, ka + AOF_KH * 2);
                ldsm4(bL, ka + AOF_KL * 2);
                #pragma unroll
                for (int tt = 0; tt < 2; ++tt) {
                    int j = p * 2 + tt;
                    uint32_t b0 = bH[tt], b1 = bH[tt + 2];
                    uint32_t l0 = bL[tt], l1 = bL[tt + 2];
                    mma16816(sacc[j], aH, b0, b1);
                    mma16816(sacc[j], aL, b0, b1);
                    mma16816(sacc[j], aH, l0, l1);
                }
            }
        }

        // ---- online softmax (rows: lane>>2 and +8) ----
        float alpha[2];
        #pragma unroll
        for (int hf = 0; hf < 2; ++hf) {
            float mv = mrow[hf];
            #pragma unroll
            for (int j = 0; j < 8; ++j) {
                sacc[j][2*hf]   *= scale;
                sacc[j][2*hf+1] *= scale;
                mv = fmaxf(mv, fmaxf(sacc[j][2*hf], sacc[j][2*hf+1]));
            }
            mv = fmaxf(mv, __shfl_xor_sync(0xffffffffu, mv, 1));
            mv = fmaxf(mv, __shfl_xor_sync(0xffffffffu, mv, 2));
            alpha[hf] = __expf(mrow[hf] - mv);
            float ls = 0.f;
            #pragma unroll
            for (int j = 0; j < 8; ++j) {
                sacc[j][2*hf]   = __expf(sacc[j][2*hf]   - mv);
                sacc[j][2*hf+1] = __expf(sacc[j][2*hf+1] - mv);
                ls += sacc[j][2*hf] + sacc[j][2*hf+1];
            }
            ls += __shfl_xor_sync(0xffffffffu, ls, 1);
            ls += __shfl_xor_sync(0xffffffffu, ls, 2);
            lrow[hf] = lrow[hf] * alpha[hf] + ls;
            mrow[hf] = mv;
            #pragma unroll
            for (int j = 0; j < 8; ++j) {
                oacc[j][2*hf]   *= alpha[hf];
                oacc[j][2*hf+1] *= alpha[hf];
            }
        }

        // ---- repack P (C-fragment -> A-fragment), hi/lo ----
        uint32_t pH[4][4], pL[4][4];
        #pragma unroll
        for (int kk = 0; kk < 4; ++kk) {
            int j0 = 2 * kk, j1 = 2 * kk + 1;
            float v00 = sacc[j0][0], v01 = sacc[j0][1];
            float v02 = sacc[j0][2], v03 = sacc[j0][3];
            float v10 = sacc[j1][0], v11 = sacc[j1][1];
            float v12 = sacc[j1][2], v13 = sacc[j1][3];
            pH[kk][0] = pack_bf2(v00, v01);
            pH[kk][1] = pack_bf2(v02, v03);
            pH[kk][2] = pack_bf2(v10, v11);
            pH[kk][3] = pack_bf2(v12, v13);
            pL[kk][0] = pack_bf2(v00 - bf_hi(v00), v01 - bf_hi(v01));
            pL[kk][1] = pack_bf2(v02 - bf_hi(v02), v03 - bf_hi(v03));
            pL[kk][2] = pack_bf2(v10 - bf_hi(v10), v11 - bf_hi(v11));
            pL[kk][3] = pack_bf2(v12 - bf_hi(v12), v13 - bf_hi(v13));
        }

        // ---- PV: O += P[16x64] . V[64x64] ----
        #pragma unroll
        for (int kk = 0; kk < 4; ++kk) {
            #pragma unroll
            for (int p = 0; p < 4; ++p) {
                uint32_t va = kvb + kk * 16 * QST * 2 + lmo + p * 32;
                uint32_t vH[4], vL[4];
                ldsm4t(vH, va + AOF_VH * 2);
                ldsm4t(vL, va + AOF_VL * 2);
                #pragma unroll
                for (int tt = 0; tt < 2; ++tt) {
                    int j = p * 2 + tt;
                    uint32_t b0 = vH[tt * 2], b1 = vH[tt * 2 + 1];
                    uint32_t l0 = vL[tt * 2], l1 = vL[tt * 2 + 1];
                    mma16816(oacc[j], pH[kk], b0, b1);
                    mma16816(oacc[j], pL[kk], b0, b1);
                    mma16816(oacc[j], pH[kk], l0, l1);
                }
            }
        }

        if (t + 1 < NT) CP_WAIT0();
        __syncthreads();
    }

    // ---- epilogue ----
    #pragma unroll
    for (int hf = 0; hf < 2; ++hf) {
        float il = 1.0f / lrow[hf];
        int row = qbase + wm + (lane >> 2) + hf * 8;
        #pragma unroll
        for (int j = 0; j < 8; ++j) {
            int col = hcol + j * 8 + (lane & 3) * 2;
            float v0 = oacc[j][2*hf]   * il;
            float v1 = oacc[j][2*hf+1] * il;
            *reinterpret_cast<uint32_t*>(&Ohi[(size_t)row * DMODEL + col]) = pack_bf2(v0, v1);
            *reinterpret_cast<uint32_t*>(&Olo[(size_t)row * DMODEL + col]) =
                pack_bf2(v0 - bf_hi(v0), v1 - bf_hi(v1));
        }
    }
}

// ---------------- launch ----------------------------------------------------
extern "C" void kernel_launch(void* const* d_in, const int* in_sizes, int n_in,
                              void* d_out, int out_size)
{
    (void)in_sizes; (void)n_in; (void)out_size;
    const float* x    = (const float*)d_in[0];
    const float* wq   = (const float*)d_in[1];
    const float* bq   = (const float*)d_in[2];
    const float* wk   = (const float*)d_in[3];
    const float* bk   = (const float*)d_in[4];
    const float* wv   = (const float*)d_in[5];
    const float* bv   = (const float*)d_in[6];
    const float* wo   = (const float*)d_in[7];
    const float* bo   = (const float*)d_in[8];
    const float* ln1g = (const float*)d_in[9];
    const float* ln1b = (const float*)d_in[10];
    const float* w1   = (const float*)d_in[11];
    const float* b1   = (const float*)d_in[12];
    const float* w2   = (const float*)d_in[13];
    const float* b2   = (const float*)d_in[14];
    const float* ln2g = (const float*)d_in[15];
    const float* ln2b = (const float*)d_in[16];
    float* out = (float*)d_out;

    float *xn, *r1, *y;
    cudaGetSymbolAddress((void**)&xn, g_xn);
    cudaGetSymbolAddress((void**)&r1, g_r1);
    cudaGetSymbolAddress((void**)&y,  g_y);

    __nv_bfloat16 *xnh,*xnl,*yh,*yl,*qh,*ql,*kh,*kl,*vh,*vl,*ath,*atl,*hh,*hl;
    __nv_bfloat16 *wqh,*wql,*wkh,*wkl,*wvh,*wvl,*woh,*wol,*w1h,*w1l,*w2h,*w2l;
    cudaGetSymbolAddress((void**)&xnh, g_xnh); cudaGetSymbolAddress((void**)&xnl, g_xnl);
    cudaGetSymbolAddress((void**)&yh,  g_yh);  cudaGetSymbolAddress((void**)&yl,  g_yl);
    cudaGetSymbolAddress((void**)&qh,  g_qh);  cudaGetSymbolAddress((void**)&ql,  g_ql);
    cudaGetSymbolAddress((void**)&kh,  g_kh);  cudaGetSymbolAddress((void**)&kl,  g_kl);
    cudaGetSymbolAddress((void**)&vh,  g_vh);  cudaGetSymbolAddress((void**)&vl,  g_vl);
    cudaGetSymbolAddress((void**)&ath, g_ath); cudaGetSymbolAddress((void**)&atl, g_atl);
    cudaGetSymbolAddress((void**)&hh,  g_hh);  cudaGetSymbolAddress((void**)&hl,  g_hl);
    cudaGetSymbolAddress((void**)&wqh, g_wqh); cudaGetSymbolAddress((void**)&wql, g_wql);
    cudaGetSymbolAddress((void**)&wkh, g_wkh); cudaGetSymbolAddress((void**)&wkl, g_wkl);
    cudaGetSymbolAddress((void**)&wvh, g_wvh); cudaGetSymbolAddress((void**)&wvl, g_wvl);
    cudaGetSymbolAddress((void**)&woh, g_woh); cudaGetSymbolAddress((void**)&wol, g_wol);
    cudaGetSymbolAddress((void**)&w1h, g_w1h); cudaGetSymbolAddress((void**)&w1l, g_w1l);
    cudaGetSymbolAddress((void**)&w2h, g_w2h); cudaGetSymbolAddress((void**)&w2l, g_w2l);

    cudaFuncSetAttribute(attn_mma, cudaFuncAttributeMaxDynamicSharedMemorySize, ATTN_SMEM);
    cudaFuncSetAttribute(gemm_mma<EPI_SPLIT>, cudaFuncAttributeMaxDynamicSharedMemorySize, GEMM_SMEM);
    cudaFuncSetAttribute(gemm_mma<EPI_RES>,   cudaFuncAttributeMaxDynamicSharedMemorySize, GEMM_SMEM);
    cudaFuncSetAttribute(gemm_mma<EPI_GELUS>, cudaFuncAttributeMaxDynamicSharedMemorySize, GEMM_SMEM);

    int nDD4 = DMODEL*DMODEL/4, nFD4 = FFDIM*DMODEL/4;
    split_kernel<<<(nDD4+255)/256, 256>>>(wq, wqh, wql, nDD4);
    split_kernel<<<(nDD4+255)/256, 256>>>(wk, wkh, wkl, nDD4);
    split_kernel<<<(nDD4+255)/256, 256>>>(wv, wvh, wvl, nDD4);
    split_kernel<<<(nDD4+255)/256, 256>>>(wo, woh, wol, nDD4);
    split_kernel<<<(nFD4+255)/256, 256>>>(w1, w1h, w1l, nFD4);
    split_kernel<<<(nFD4+255)/256, 256>>>(w2, w2h, w2l, nFD4);

    dim3 gD(DMODEL/128, MROWS/128);
    dim3 gF(FFDIM/128,  MROWS/128);

    ln_split_kernel<<<MROWS, 256>>>(x, ln1g, ln1b, xn, xnh, xnl);
    gemm_mma<EPI_SPLIT><<<gD, 256, GEMM_SMEM>>>(xnh, xnl, wqh, wql, bq, nullptr, nullptr, qh, ql, MROWS, DMODEL, DMODEL);
    gemm_mma<EPI_SPLIT><<<gD, 256, GEMM_SMEM>>>(xnh, xnl, wkh, wkl, bk, nullptr, nullptr, kh, kl, MROWS, DMODEL, DMODEL);
    gemm_mma<EPI_SPLIT><<<gD, 256, GEMM_SMEM>>>(xnh, xnl, wvh, wvl, bv, nullptr, nullptr, vh, vl, MROWS, DMODEL, DMODEL);
    attn_mma<<<dim3(SEQ/128, BATCH*NHEAD), 256, ATTN_SMEM>>>(qh, ql, kh, kl, vh, vl, ath, atl);
    gemm_mma<EPI_RES><<<gD, 256, GEMM_SMEM>>>(ath, atl, woh, wol, bo, xn, r1, nullptr, nullptr, MROWS, DMODEL, DMODEL);
    ln_split_kernel<<<MROWS, 256>>>(r1, ln2g, ln2b, y, yh, yl);
    gemm_mma<EPI_GELUS><<<gF, 256, GEMM_SMEM>>>(yh, yl, w1h, w1l, b1, nullptr, nullptr, hh, hl, MROWS, FFDIM, DMODEL);
    gemm_mma<EPI_RES><<<gD, 256, GEMM_SMEM>>>(hh, hl, w2h, w2l, b2, y, out, nullptr, nullptr, MROWS, DMODEL, FFDIM);
}

// round 7
// speedup vs baseline: 8.6107x; 1.4256x over previous
#include <cuda_runtime.h>
#include <cuda_fp16.h>
#include <math.h>
#include <stdint.h>

// Problem constants
#define BATCH 2
#define SEQ   2048
#define DMODEL 1024
#define NHEAD 16
#define HDIM  64
#define FFDIM 4096
#define MROWS (BATCH*SEQ)   // 4096
#define LN_EPS 1e-5f

// ---------------- scratch buffers ------------------------------------------
__device__ float g_xn [MROWS*DMODEL];
__device__ float g_r1 [MROWS*DMODEL];
__device__ float g_y  [MROWS*DMODEL];

__device__ __half g_xnh[MROWS*DMODEL], g_xnl[MROWS*DMODEL];
__device__ __half g_yh [MROWS*DMODEL], g_yl [MROWS*DMODEL];
__device__ __half g_qh [MROWS*DMODEL], g_ql [MROWS*DMODEL];
__device__ __half g_kh [MROWS*DMODEL];
__device__ __half g_vh [MROWS*DMODEL];
__device__ __half g_ath[MROWS*DMODEL], g_atl[MROWS*DMODEL];
__device__ __half g_hh [MROWS*FFDIM],  g_hl [MROWS*FFDIM];

__device__ __half g_wqh[DMODEL*DMODEL];
__device__ __half g_wkh[DMODEL*DMODEL];
__device__ __half g_wvh[DMODEL*DMODEL];
__device__ __half g_woh[DMODEL*DMODEL];
__device__ __half g_w1h[FFDIM*DMODEL];
__device__ __half g_w2h[DMODEL*FFDIM];

// ---------------- helpers ---------------------------------------------------
__device__ __forceinline__ uint32_t smem_to_u32(const void* p) {
    uint32_t a;
    asm("{ .reg .u64 t; cvta.to.shared.u64 t, %1; cvt.u32.u64 %0, t; }"
        : "=r"(a) : "l"(p));
    return a;
}
__device__ __forceinline__ void cp16(uint32_t d, const void* s) {
    asm volatile("cp.async.cg.shared.global [%0], [%1], 16;" :: "r"(d), "l"(s) : "memory");
}
#define CP_COMMIT() asm volatile("cp.async.commit_group;" ::: "memory")
#define CP_WAIT0()  asm volatile("cp.async.wait_group 0;" ::: "memory")

__device__ __forceinline__ void ldsm4(uint32_t* r, uint32_t addr) {
    asm volatile("ldmatrix.sync.aligned.m8n8.x4.shared.b16 {%0,%1,%2,%3}, [%4];"
        : "=r"(r[0]), "=r"(r[1]), "=r"(r[2]), "=r"(r[3]) : "r"(addr));
}
__device__ __forceinline__ void ldsm4t(uint32_t* r, uint32_t addr) {
    asm volatile("ldmatrix.sync.aligned.m8n8.x4.trans.shared.b16 {%0,%1,%2,%3}, [%4];"
        : "=r"(r[0]), "=r"(r[1]), "=r"(r[2]), "=r"(r[3]) : "r"(addr));
}
__device__ __forceinline__ void mma16816(float* c, const uint32_t* a,
                                         uint32_t b0, uint32_t b1) {
    asm volatile("mma.sync.aligned.m16n8k16.row.col.f32.f16.f16.f32 "
        "{%0,%1,%2,%3}, {%4,%5,%6,%7}, {%8,%9}, {%0,%1,%2,%3};"
        : "+f"(c[0]), "+f"(c[1]), "+f"(c[2]), "+f"(c[3])
        : "r"(a[0]), "r"(a[1]), "r"(a[2]), "r"(a[3]), "r"(b0), "r"(b1));
}

__device__ __forceinline__ uint32_t pack_hf2(float a, float b) {
    __half2 t;
    t.x = __float2half_rn(a);
    t.y = __float2half_rn(b);
    uint32_t u;
    *reinterpret_cast<__half2*>(&u) = t;
    return u;
}
__device__ __forceinline__ float hf_hi(float v) {
    return __half2float(__float2half_rn(v));
}
__device__ __forceinline__ float gelu_exact(float v) {
    return 0.5f * v * (1.0f + erff(v * 0.70710678118654752440f));
}

// ---------------- weight fp16 convert ----------------------------------------
__global__ __launch_bounds__(256)
void conv_kernel(const float* __restrict__ s, __half* __restrict__ hi, int n4)
{
    int i = blockIdx.x * blockDim.x + threadIdx.x;
    if (i >= n4) return;
    float4 v = reinterpret_cast<const float4*>(s)[i];
    uint2 hu;
    hu.x = pack_hf2(v.x, v.y);
    hu.y = pack_hf2(v.z, v.w);
    reinterpret_cast<uint2*>(hi)[i] = hu;
}

// ---------------- LayerNorm + dual split ------------------------------------
__global__ __launch_bounds__(256)
void ln_split_kernel(const float* __restrict__ x, const float* __restrict__ g,
                     const float* __restrict__ b, float* __restrict__ y,
                     __half* __restrict__ yh, __half* __restrict__ yl)
{
    int row = blockIdx.x;
    int tid = threadIdx.x;
    const float4* xr = reinterpret_cast<const float4*>(x + (size_t)row * DMODEL);
    float4 v = xr[tid];

    float s = v.x + v.y + v.z + v.w;
    float q = v.x*v.x + v.y*v.y + v.z*v.z + v.w*v.w;
    #pragma unroll
    for (int o = 16; o > 0; o >>= 1) {
        s += __shfl_down_sync(0xffffffffu, s, o);
        q += __shfl_down_sync(0xffffffffu, q, o);
    }
    __shared__ float ss[8], sq[8];
    int wid = tid >> 5, lane = tid & 31;
    if (lane == 0) { ss[wid] = s; sq[wid] = q; }
    __syncthreads();
    float tot = 0.f, totq = 0.f;
    #pragma unroll
    for (int i = 0; i < 8; ++i) { tot += ss[i]; totq += sq[i]; }

    float mu  = tot * (1.0f / DMODEL);
    float var = totq * (1.0f / DMODEL) - mu * mu;
    float rs  = rsqrtf(var + LN_EPS);

    float4 gg = reinterpret_cast<const float4*>(g)[tid];
    float4 bb = reinterpret_cast<const float4*>(b)[tid];
    float4 o;
    o.x = (v.x - mu) * rs * gg.x + bb.x;
    o.y = (v.y - mu) * rs * gg.y + bb.y;
    o.z = (v.z - mu) * rs * gg.z + bb.z;
    o.w = (v.w - mu) * rs * gg.w + bb.w;
    reinterpret_cast<float4*>(y + (size_t)row * DMODEL)[tid] = o;

    uint2 hu, lu;
    hu.x = pack_hf2(o.x, o.y);
    hu.y = pack_hf2(o.z, o.w);
    lu.x = pack_hf2(o.x - hf_hi(o.x), o.y - hf_hi(o.y));
    lu.y = pack_hf2(o.z - hf_hi(o.z), o.w - hf_hi(o.w));
    reinterpret_cast<uint2*>(yh + (size_t)row * DMODEL)[tid] = hu;
    reinterpret_cast<uint2*>(yl + (size_t)row * DMODEL)[tid] = lu;
}

// ---------------- warp-MMA GEMM ---------------------------------------------
// C[M,N] = (Ah+Al)[M,K] @ W[N,K]^T  (fp16, 2 MMAs per position)
#define EPI_RES    1
#define EPI_GELUS  2
#define EPI_SPLIT  3
#define EPI_SINGLE 4

#define GROWB  80
#define MATB   (128 * GROWB)
#define OFF_AH 0
#define OFF_AL MATB
#define OFF_W  (2*MATB)
#define STAGEB (3*MATB)
#define GEMM_SMEM (2*STAGEB)   // 61440

template<int EPI>
__global__ __launch_bounds__(256, 1)
void gemm_mma(const __half* __restrict__ Ah, const __half* __restrict__ Al,
              const __half* __restrict__ W,
              const float* __restrict__ bias, const float* __restrict__ res,
              float* __restrict__ Cf, __half* __restrict__ Chi,
              __half* __restrict__ Clo, int M, int N, int K)
{
    extern __shared__ char smc[];
    uint32_t sb = smem_to_u32(smc);
    int tid  = threadIdx.x;
    int lane = tid & 31;
    int warp = tid >> 5;
    int n0 = blockIdx.x * 128;
    int m0 = blockIdx.y * 128;
    int wm = (warp >> 2) * 64;
    int wn = (warp & 3) * 32;

    int r  = tid >> 1;
    int hf = tid & 1;
    const __half* gAh = Ah + (size_t)(m0 + r) * K + hf * 16;
    const __half* gAl = Al + (size_t)(m0 + r) * K + hf * 16;
    const __half* gW  = W  + (size_t)(n0 + r) * K + hf * 16;
    uint32_t sdst = sb + r * GROWB + hf * 32;

    float acc[4][4][4];
    #pragma unroll
    for (int mi = 0; mi < 4; ++mi)
        #pragma unroll
        for (int nj = 0; nj < 4; ++nj)
            #pragma unroll
            for (int e = 0; e < 4; ++e) acc[mi][nj][e] = 0.f;

    uint32_t lmo = (uint32_t)((lane & 15) * GROWB + (lane >> 4) * 16);
    int nch = K / 32;

    {
        cp16(sdst + OFF_AH, gAh);  cp16(sdst + OFF_AH + 16, gAh + 8);
        cp16(sdst + OFF_AL, gAl);  cp16(sdst + OFF_AL + 16, gAl + 8);
        cp16(sdst + OFF_W,  gW);   cp16(sdst + OFF_W  + 16, gW  + 8);
        CP_COMMIT();
        CP_WAIT0();
        __syncthreads();
    }

    for (int c = 0; c < nch; ++c) {
        int s = c & 1;
        if (c + 1 < nch) {
            size_t ko = (size_t)(c + 1) * 32;
            uint32_t d2 = sdst + (s ^ 1) * STAGEB;
            cp16(d2 + OFF_AH, gAh + ko);  cp16(d2 + OFF_AH + 16, gAh + ko + 8);
            cp16(d2 + OFF_AL, gAl + ko);  cp16(d2 + OFF_AL + 16, gAl + ko + 8);
            cp16(d2 + OFF_W,  gW  + ko);  cp16(d2 + OFF_W  + 16, gW  + ko + 8);
            CP_COMMIT();
        }

        uint32_t stgb = sb + s * STAGEB;
        #pragma unroll
        for (int ks = 0; ks < 2; ++ks) {
            uint32_t kb = ks * 32;
            uint32_t aH[4][4], aL[4][4], bW[2][4];
            #pragma unroll
            for (int mi = 0; mi < 4; ++mi) {
                uint32_t ra = (wm + mi * 16) * GROWB + lmo + kb;
                ldsm4(aH[mi], stgb + OFF_AH + ra);
                ldsm4(aL[mi], stgb + OFF_AL + ra);
            }
            #pragma unroll
            for (int p = 0; p < 2; ++p) {
                uint32_t rb = (wn + p * 16) * GROWB + lmo + kb;
                ldsm4(bW[p], stgb + OFF_W + rb);
            }
            #pragma unroll
            for (int mi = 0; mi < 4; ++mi) {
                #pragma unroll
                for (int nj = 0; nj < 4; ++nj) {
                    uint32_t b0 = bW[nj >> 1][nj & 1];
                    uint32_t b1 = bW[nj >> 1][(nj & 1) + 2];
                    mma16816(acc[mi][nj], aH[mi], b0, b1);
                    mma16816(acc[mi][nj], aL[mi], b0, b1);
                }
            }
        }

        if (c + 1 < nch) CP_WAIT0();
        __syncthreads();
    }

    int gid  = lane >> 2;
    int tid4 = lane & 3;
    float b2v[4][2];
    #pragma unroll
    for (int nj = 0; nj < 4; ++nj) {
        int col = n0 + wn + nj * 8 + tid4 * 2;
        b2v[nj][0] = bias[col];
        b2v[nj][1] = bias[col + 1];
    }
    #pragma unroll
    for (int mi = 0; mi < 4; ++mi) {
        #pragma unroll
        for (int half = 0; half < 2; ++half) {
            int row = m0 + wm + mi * 16 + gid + half * 8;
            #pragma unroll
            for (int nj = 0; nj < 4; ++nj) {
                int col = n0 + wn + nj * 8 + tid4 * 2;
                float v0 = acc[mi][nj][half * 2 + 0] + b2v[nj][0];
                float v1 = acc[mi][nj][half * 2 + 1] + b2v[nj][1];
                if (EPI == EPI_RES) {
                    float2 rv = *reinterpret_cast<const float2*>(&res[(size_t)row * N + col]);
                    v0 += rv.x; v1 += rv.y;
                    float2 o; o.x = v0; o.y = v1;
                    *reinterpret_cast<float2*>(&Cf[(size_t)row * N + col]) = o;
                } else if (EPI == EPI_SINGLE) {
                    *reinterpret_cast<uint32_t*>(&Chi[(size_t)row * N + col]) = pack_hf2(v0, v1);
                } else {
                    if (EPI == EPI_GELUS) { v0 = gelu_exact(v0); v1 = gelu_exact(v1); }
                    *reinterpret_cast<uint32_t*>(&Chi[(size_t)row * N + col]) = pack_hf2(v0, v1);
                    *reinterpret_cast<uint32_t*>(&Clo[(size_t)row * N + col]) =
                        pack_hf2(v0 - hf_hi(v0), v1 - hf_hi(v1));
                }
            }
        }
    }
}

// ---------------- MMA flash attention ---------------------------------------
// grid = (SEQ/128, B*H), 256 threads (8 warps, 16 query rows each).
// Q dual (hi/lo), K single, V single; P dual in-register. 2 MMAs per position.
#define QST 72                         // smem row stride in fp16 elems (144B)
#define AQH 0
#define AQL (128*QST)
#define AKV0 (2*128*QST)               // stage base
#define KVSTG (2*64*QST)               // elems per stage (Kh, Vh)
#define AOF_KH 0
#define AOF_VH (64*QST)
#define ATTN_SMEM ((2*128*QST + 2*KVSTG) * 2)   // 73728 bytes

__global__ __launch_bounds__(256, 1)
void attn_mma(const __half* __restrict__ Qh, const __half* __restrict__ Ql,
              const __half* __restrict__ Kh, const __half* __restrict__ Vh,
              __half* __restrict__ Ohi, __half* __restrict__ Olo)
{
    extern __shared__ __half sma[];
    uint32_t sb = smem_to_u32(sma);

    int tid  = threadIdx.x;
    int lane = tid & 31;
    int warp = tid >> 5;
    int bh = blockIdx.y;
    int b = bh >> 4, h = bh & 15;
    int qbase  = b * SEQ + blockIdx.x * 128;
    int kvbase = b * SEQ;
    int hcol   = h * HDIM;
    int wm = warp * 16;

    // ---- load Q (128 rows x 64 cols, hi+lo): 2 threads per row ----
    {
        int rr = tid >> 1, cc2 = (tid & 1) * 4;
        const __half* gq = Qh + (size_t)(qbase + rr) * DMODEL + hcol + cc2 * 8;
        const __half* gl = Ql + (size_t)(qbase + rr) * DMODEL + hcol + cc2 * 8;
        uint32_t dq = sb + (rr * QST + cc2 * 8) * 2;
        #pragma unroll
        for (int c = 0; c < 4; ++c) {
            cp16(dq + AQH * 2 + c * 16, gq + c * 8);
            cp16(dq + AQL * 2 + c * 16, gl + c * 8);
        }
    }

    // ---- KV stage loader: 4 threads per row (64 rows per tile) ----
    int krr = tid >> 2;              // 0..63
    int kc4 = (tid & 3) * 16;        // elem offset within 64-col row
    uint32_t kdst = sb + (krr * QST + kc4) * 2;
    size_t kgo = (size_t)hcol + kc4;

    {   // prologue stage 0 (tile 0)
        size_t grow = (size_t)(kvbase + krr) * DMODEL + kgo;
        uint32_t st = kdst + AKV0 * 2;
        cp16(st + AOF_KH*2, Kh + grow);  cp16(st + AOF_KH*2 + 16, Kh + grow + 8);
        cp16(st + AOF_VH*2, Vh + grow);  cp16(st + AOF_VH*2 + 16, Vh + grow + 8);
        CP_COMMIT();
        CP_WAIT0();
        __syncthreads();
    }

    float oacc[8][4];
    #pragma unroll
    for (int j = 0; j < 8; ++j)
        #pragma unroll
        for (int e = 0; e < 4; ++e) oacc[j][e] = 0.f;
    float mrow[2] = {-1e30f, -1e30f};
    float lrow[2] = {0.f, 0.f};

    uint32_t lmo = (uint32_t)((lane & 15) * QST * 2 + (lane >> 4) * 16);
    const float scale = 0.125f;

    const int NT = SEQ / 64;
    for (int t = 0; t < NT; ++t) {
        int s = t & 1;
        if (t + 1 < NT) {
            size_t grow = (size_t)(kvbase + (t + 1) * 64 + krr) * DMODEL + kgo;
            uint32_t st = kdst + (AKV0 + (s ^ 1) * KVSTG) * 2;
            cp16(st + AOF_KH*2, Kh + grow);  cp16(st + AOF_KH*2 + 16, Kh + grow + 8);
            cp16(st + AOF_VH*2, Vh + grow);  cp16(st + AOF_VH*2 + 16, Vh + grow + 8);
            CP_COMMIT();
        }

        uint32_t kvb = sb + (AKV0 + s * KVSTG) * 2;

        // ---- scores: S[16 x 64] = Q_tile . K_tile^T ----
        float sacc[8][4];
        #pragma unroll
        for (int j = 0; j < 8; ++j)
            #pragma unroll
            for (int e = 0; e < 4; ++e) sacc[j][e] = 0.f;

        #pragma unroll
        for (int kk = 0; kk < 4; ++kk) {
            uint32_t aH[4], aL[4], bK[4];
            uint32_t qa = sb + wm * QST * 2 + lmo + kk * 32;
            ldsm4(aH, qa + AQH * 2);
            ldsm4(aL, qa + AQL * 2);
            #pragma unroll
            for (int p = 0; p < 4; ++p) {
                uint32_t ka = kvb + p * 16 * QST * 2 + lmo + kk * 32;
                ldsm4(bK, ka + AOF_KH * 2);
                #pragma unroll
                for (int tt = 0; tt < 2; ++tt) {
                    int j = p * 2 + tt;
                    uint32_t b0 = bK[tt], b1 = bK[tt + 2];
                    mma16816(sacc[j], aH, b0, b1);
                    mma16816(sacc[j], aL, b0, b1);
                }
            }
        }

        // ---- online softmax (rows: lane>>2 and +8) ----
        float alpha[2];
        #pragma unroll
        for (int hf = 0; hf < 2; ++hf) {
            float mv = mrow[hf];
            #pragma unroll
            for (int j = 0; j < 8; ++j) {
                sacc[j][2*hf]   *= scale;
                sacc[j][2*hf+1] *= scale;
                mv = fmaxf(mv, fmaxf(sacc[j][2*hf], sacc[j][2*hf+1]));
            }
            mv = fmaxf(mv, __shfl_xor_sync(0xffffffffu, mv, 1));
            mv = fmaxf(mv, __shfl_xor_sync(0xffffffffu, mv, 2));
            alpha[hf] = __expf(mrow[hf] - mv);
            float ls = 0.f;
            #pragma unroll
            for (int j = 0; j < 8; ++j) {
                sacc[j][2*hf]   = __expf(sacc[j][2*hf]   - mv);
                sacc[j][2*hf+1] = __expf(sacc[j][2*hf+1] - mv);
                ls += sacc[j][2*hf] + sacc[j][2*hf+1];
            }
            ls += __shfl_xor_sync(0xffffffffu, ls, 1);
            ls += __shfl_xor_sync(0xffffffffu, ls, 2);
            lrow[hf] = lrow[hf] * alpha[hf] + ls;
            mrow[hf] = mv;
            #pragma unroll
            for (int j = 0; j < 8; ++j) {
                oacc[j][2*hf]   *= alpha[hf];
                oacc[j][2*hf+1] *= alpha[hf];
            }
        }

        // ---- repack P (C-fragment -> A-fragment), hi/lo ----
        uint32_t pH[4][4], pL[4][4];
        #pragma unroll
        for (int kk = 0; kk < 4; ++kk) {
            int j0 = 2 * kk, j1 = 2 * kk + 1;
            float v00 = sacc[j0][0], v01 = sacc[j0][1];
            float v02 = sacc[j0][2], v03 = sacc[j0][3];
            float v10 = sacc[j1][0], v11 = sacc[j1][1];
            float v12 = sacc[j1][2], v13 = sacc[j1][3];
            pH[kk][0] = pack_hf2(v00, v01);
            pH[kk][1] = pack_hf2(v02, v03);
            pH[kk][2] = pack_hf2(v10, v11);
            pH[kk][3] = pack_hf2(v12, v13);
            pL[kk][0] = pack_hf2(v00 - hf_hi(v00), v01 - hf_hi(v01));
            pL[kk][1] = pack_hf2(v02 - hf_hi(v02), v03 - hf_hi(v03));
            pL[kk][2] = pack_hf2(v10 - hf_hi(v10), v11 - hf_hi(v11));
            pL[kk][3] = pack_hf2(v12 - hf_hi(v12), v13 - hf_hi(v13));
        }

        // ---- PV: O += P[16x64] . V[64x64] ----
        #pragma unroll
        for (int kk = 0; kk < 4; ++kk) {
            #pragma unroll
            for (int p = 0; p < 4; ++p) {
                uint32_t va = kvb + kk * 16 * QST * 2 + lmo + p * 32;
                uint32_t vV[4];
                ldsm4t(vV, va + AOF_VH * 2);
                #pragma unroll
                for (int tt = 0; tt < 2; ++tt) {
                    int j = p * 2 + tt;
                    uint32_t b0 = vV[tt * 2], b1 = vV[tt * 2 + 1];
                    mma16816(oacc[j], pH[kk], b0, b1);
                    mma16816(oacc[j], pL[kk], b0, b1);
                }
            }
        }

        if (t + 1 < NT) CP_WAIT0();
        __syncthreads();
    }

    // ---- epilogue ----
    #pragma unroll
    for (int hf = 0; hf < 2; ++hf) {
        float il = 1.0f / lrow[hf];
        int row = qbase + wm + (lane >> 2) + hf * 8;
        #pragma unroll
        for (int j = 0; j < 8; ++j) {
            int col = hcol + j * 8 + (lane & 3) * 2;
            float v0 = oacc[j][2*hf]   * il;
            float v1 = oacc[j][2*hf+1] * il;
            *reinterpret_cast<uint32_t*>(&Ohi[(size_t)row * DMODEL + col]) = pack_hf2(v0, v1);
            *reinterpret_cast<uint32_t*>(&Olo[(size_t)row * DMODEL + col]) =
                pack_hf2(v0 - hf_hi(v0), v1 - hf_hi(v1));
        }
    }
}

// ---------------- launch ----------------------------------------------------
extern "C" void kernel_launch(void* const* d_in, const int* in_sizes, int n_in,
                              void* d_out, int out_size)
{
    (void)in_sizes; (void)n_in; (void)out_size;
    const float* x    = (const float*)d_in[0];
    const float* wq   = (const float*)d_in[1];
    const float* bq   = (const float*)d_in[2];
    const float* wk   = (const float*)d_in[3];
    const float* bk   = (const float*)d_in[4];
    const float* wv   = (const float*)d_in[5];
    const float* bv   = (const float*)d_in[6];
    const float* wo   = (const float*)d_in[7];
    const float* bo   = (const float*)d_in[8];
    const float* ln1g = (const float*)d_in[9];
    const float* ln1b = (const float*)d_in[10];
    const float* w1   = (const float*)d_in[11];
    const float* b1   = (const float*)d_in[12];
    const float* w2   = (const float*)d_in[13];
    const float* b2   = (const float*)d_in[14];
    const float* ln2g = (const float*)d_in[15];
    const float* ln2b = (const float*)d_in[16];
    float* out = (float*)d_out;

    float *xn, *r1, *y;
    cudaGetSymbolAddress((void**)&xn, g_xn);
    cudaGetSymbolAddress((void**)&r1, g_r1);
    cudaGetSymbolAddress((void**)&y,  g_y);

    __half *xnh,*xnl,*yh,*yl,*qh,*ql,*kh,*vh,*ath,*atl,*hh,*hl;
    __half *wqh,*wkh,*wvh,*woh,*w1h,*w2h;
    cudaGetSymbolAddress((void**)&xnh, g_xnh); cudaGetSymbolAddress((void**)&xnl, g_xnl);
    cudaGetSymbolAddress((void**)&yh,  g_yh);  cudaGetSymbolAddress((void**)&yl,  g_yl);
    cudaGetSymbolAddress((void**)&qh,  g_qh);  cudaGetSymbolAddress((void**)&ql,  g_ql);
    cudaGetSymbolAddress((void**)&kh,  g_kh);  cudaGetSymbolAddress((void**)&vh,  g_vh);
    cudaGetSymbolAddress((void**)&ath, g_ath); cudaGetSymbolAddress((void**)&atl, g_atl);
    cudaGetSymbolAddress((void**)&hh,  g_hh);  cudaGetSymbolAddress((void**)&hl,  g_hl);
    cudaGetSymbolAddress((void**)&wqh, g_wqh); cudaGetSymbolAddress((void**)&wkh, g_wkh);
    cudaGetSymbolAddress((void**)&wvh, g_wvh); cudaGetSymbolAddress((void**)&woh, g_woh);
    cudaGetSymbolAddress((void**)&w1h, g_w1h); cudaGetSymbolAddress((void**)&w2h, g_w2h);

    cudaFuncSetAttribute(attn_mma, cudaFuncAttributeMaxDynamicSharedMemorySize, ATTN_SMEM);
    cudaFuncSetAttribute(gemm_mma<EPI_SPLIT>,  cudaFuncAttributeMaxDynamicSharedMemorySize, GEMM_SMEM);
    cudaFuncSetAttribute(gemm_mma<EPI_SINGLE>, cudaFuncAttributeMaxDynamicSharedMemorySize, GEMM_SMEM);
    cudaFuncSetAttribute(gemm_mma<EPI_RES>,    cudaFuncAttributeMaxDynamicSharedMemorySize, GEMM_SMEM);
    cudaFuncSetAttribute(gemm_mma<EPI_GELUS>,  cudaFuncAttributeMaxDynamicSharedMemorySize, GEMM_SMEM);

    int nDD4 = DMODEL*DMODEL/4, nFD4 = FFDIM*DMODEL/4;
    conv_kernel<<<(nDD4+255)/256, 256>>>(wq, wqh, nDD4);
    conv_kernel<<<(nDD4+255)/256, 256>>>(wk, wkh, nDD4);
    conv_kernel<<<(nDD4+255)/256, 256>>>(wv, wvh, nDD4);
    conv_kernel<<<(nDD4+255)/256, 256>>>(wo, woh, nDD4);
    conv_kernel<<<(nFD4+255)/256, 256>>>(w1, w1h, nFD4);
    conv_kernel<<<(nFD4+255)/256, 256>>>(w2, w2h, nFD4);

    dim3 gD(DMODEL/128, MROWS/128);
    dim3 gF(FFDIM/128,  MROWS/128);

    ln_split_kernel<<<MROWS, 256>>>(x, ln1g, ln1b, xn, xnh, xnl);
    gemm_mma<EPI_SPLIT><<<gD, 256, GEMM_SMEM>>>(xnh, xnl, wqh, bq, nullptr, nullptr, qh, ql, MROWS, DMODEL, DMODEL);
    gemm_mma<EPI_SINGLE><<<gD, 256, GEMM_SMEM>>>(xnh, xnl, wkh, bk, nullptr, nullptr, kh, nullptr, MROWS, DMODEL, DMODEL);
    gemm_mma<EPI_SINGLE><<<gD, 256, GEMM_SMEM>>>(xnh, xnl, wvh, bv, nullptr, nullptr, vh, nullptr, MROWS, DMODEL, DMODEL);
    attn_mma<<<dim3(SEQ/128, BATCH*NHEAD), 256, ATTN_SMEM>>>(qh, ql, kh, vh, ath, atl);
    gemm_mma<EPI_RES><<<gD, 256, GEMM_SMEM>>>(ath, atl, woh, bo, xn, r1, nullptr, nullptr, MROWS, DMODEL, DMODEL);
    ln_split_kernel<<<MROWS, 256>>>(r1, ln2g, ln2b, y, yh, yl);
    gemm_mma<EPI_GELUS><<<gF, 256, GEMM_SMEM>>>(yh, yl, w1h, b1, nullptr, nullptr, hh, hl, MROWS, FFDIM, DMODEL);
    gemm_mma<EPI_RES><<<gD, 256, GEMM_SMEM>>>(hh, hl, w2h, b2, y, out, nullptr, nullptr, MROWS, DMODEL, FFDIM);
}

// round 9
// speedup vs baseline: 15.1941x; 1.7646x over previous
#include <cuda_runtime.h>
#include <cuda_fp16.h>
#include <math.h>
#include <stdint.h>

// Problem constants
#define BATCH 2
#define SEQ   2048
#define DMODEL 1024
#define NHEAD 16
#define HDIM  64
#define FFDIM 4096
#define MROWS (BATCH*SEQ)   // 4096
#define LN_EPS 1e-5f

// ---------------- scratch buffers ------------------------------------------
__device__ float g_xn [MROWS*DMODEL];
__device__ float g_r1 [MROWS*DMODEL];
__device__ float g_y  [MROWS*DMODEL];

__device__ __half g_xnh[MROWS*DMODEL];
__device__ __half g_yh [MROWS*DMODEL];
__device__ __half g_qh [MROWS*DMODEL];
__device__ __half g_kh [MROWS*DMODEL];
__device__ __half g_vh [MROWS*DMODEL];
__device__ __half g_ath[MROWS*DMODEL];
__device__ __half g_hh [MROWS*FFDIM];

__device__ __half g_wqh[DMODEL*DMODEL];
__device__ __half g_wkh[DMODEL*DMODEL];
__device__ __half g_wvh[DMODEL*DMODEL];
__device__ __half g_woh[DMODEL*DMODEL];
__device__ __half g_w1h[FFDIM*DMODEL];
__device__ __half g_w2h[DMODEL*FFDIM];

// ---------------- helpers ---------------------------------------------------
__device__ __forceinline__ uint32_t smem_to_u32(const void* p) {
    uint32_t a;
    asm("{ .reg .u64 t; cvta.to.shared.u64 t, %1; cvt.u32.u64 %0, t; }"
        : "=r"(a) : "l"(p));
    return a;
}
__device__ __forceinline__ void cp16(uint32_t d, const void* s) {
    asm volatile("cp.async.cg.shared.global [%0], [%1], 16;" :: "r"(d), "l"(s) : "memory");
}
#define CP_COMMIT() asm volatile("cp.async.commit_group;" ::: "memory")
#define CP_WAIT0()  asm volatile("cp.async.wait_group 0;" ::: "memory")

__device__ __forceinline__ void ldsm4(uint32_t* r, uint32_t addr) {
    asm volatile("ldmatrix.sync.aligned.m8n8.x4.shared.b16 {%0,%1,%2,%3}, [%4];"
        : "=r"(r[0]), "=r"(r[1]), "=r"(r[2]), "=r"(r[3]) : "r"(addr));
}
__device__ __forceinline__ void ldsm4t(uint32_t* r, uint32_t addr) {
    asm volatile("ldmatrix.sync.aligned.m8n8.x4.trans.shared.b16 {%0,%1,%2,%3}, [%4];"
        : "=r"(r[0]), "=r"(r[1]), "=r"(r[2]), "=r"(r[3]) : "r"(addr));
}
__device__ __forceinline__ void mma16816(float* c, const uint32_t* a,
                                         uint32_t b0, uint32_t b1) {
    asm volatile("mma.sync.aligned.m16n8k16.row.col.f32.f16.f16.f32 "
        "{%0,%1,%2,%3}, {%4,%5,%6,%7}, {%8,%9}, {%0,%1,%2,%3};"
        : "+f"(c[0]), "+f"(c[1]), "+f"(c[2]), "+f"(c[3])
        : "r"(a[0]), "r"(a[1]), "r"(a[2]), "r"(a[3]), "r"(b0), "r"(b1));
}

__device__ __forceinline__ uint32_t pack_hf2(float a, float b) {
    __half2 t;
    t.x = __float2half_rn(a);
    t.y = __float2half_rn(b);
    uint32_t u;
    *reinterpret_cast<__half2*>(&u) = t;
    return u;
}
__device__ __forceinline__ float gelu_exact(float v) {
    return 0.5f * v * (1.0f + erff(v * 0.70710678118654752440f));
}

// ---------------- weight fp16 convert ----------------------------------------
__global__ __launch_bounds__(256)
void conv_kernel(const float* __restrict__ s, __half* __restrict__ hi, int n4)
{
    int i = blockIdx.x * blockDim.x + threadIdx.x;
    if (i >= n4) return;
    float4 v = reinterpret_cast<const float4*>(s)[i];
    uint2 hu;
    hu.x = pack_hf2(v.x, v.y);
    hu.y = pack_hf2(v.z, v.w);
    reinterpret_cast<uint2*>(hi)[i] = hu;
}

// ---------------- LayerNorm + fp16 out ---------------------------------------
__global__ __launch_bounds__(256)
void ln_conv_kernel(const float* __restrict__ x, const float* __restrict__ g,
                    const float* __restrict__ b, float* __restrict__ y,
                    __half* __restrict__ yh)
{
    int row = blockIdx.x;
    int tid = threadIdx.x;
    const float4* xr = reinterpret_cast<const float4*>(x + (size_t)row * DMODEL);
    float4 v = xr[tid];

    float s = v.x + v.y + v.z + v.w;
    float q = v.x*v.x + v.y*v.y + v.z*v.z + v.w*v.w;
    #pragma unroll
    for (int o = 16; o > 0; o >>= 1) {
        s += __shfl_down_sync(0xffffffffu, s, o);
        q += __shfl_down_sync(0xffffffffu, q, o);
    }
    __shared__ float ss[8], sq[8];
    int wid = tid >> 5, lane = tid & 31;
    if (lane == 0) { ss[wid] = s; sq[wid] = q; }
    __syncthreads();
    float tot = 0.f, totq = 0.f;
    #pragma unroll
    for (int i = 0; i < 8; ++i) { tot += ss[i]; totq += sq[i]; }

    float mu  = tot * (1.0f / DMODEL);
    float var = totq * (1.0f / DMODEL) - mu * mu;
    float rs  = rsqrtf(var + LN_EPS);

    float4 gg = reinterpret_cast<const float4*>(g)[tid];
    float4 bb = reinterpret_cast<const float4*>(b)[tid];
    float4 o;
    o.x = (v.x - mu) * rs * gg.x + bb.x;
    o.y = (v.y - mu) * rs * gg.y + bb.y;
    o.z = (v.z - mu) * rs * gg.z + bb.z;
    o.w = (v.w - mu) * rs * gg.w + bb.w;
    reinterpret_cast<float4*>(y + (size_t)row * DMODEL)[tid] = o;

    uint2 hu;
    hu.x = pack_hf2(o.x, o.y);
    hu.y = pack_hf2(o.z, o.w);
    reinterpret_cast<uint2*>(yh + (size_t)row * DMODEL)[tid] = hu;
}

// ---------------- warp-MMA GEMM ---------------------------------------------
// C[M,N] = A[M,K] @ W[N,K]^T  (fp16, 1 MMA per position)
#define EPI_RES    1
#define EPI_GELUS  2
#define EPI_SINGLE 4

#define GROWB  80
#define MATB   (128 * GROWB)
#define OFF_A  0
#define OFF_W  MATB
#define STAGEB (2*MATB)        // 20480
#define GEMM_SMEM (2*STAGEB)   // 40960

template<int EPI>
__global__ __launch_bounds__(256, 2)
void gemm_mma(const __half* __restrict__ A, const __half* __restrict__ W,
              const float* __restrict__ bias, const float* __restrict__ res,
              float* __restrict__ Cf, __half* __restrict__ Chi,
              int M, int N, int K)
{
    extern __shared__ char smc[];
    uint32_t sb = smem_to_u32(smc);
    int tid  = threadIdx.x;
    int lane = tid & 31;
    int warp = tid >> 5;
    int n0 = blockIdx.x * 128;
    int m0 = blockIdx.y * 128;
    int wm = (warp >> 2) * 64;
    int wn = (warp & 3) * 32;

    int r  = tid >> 1;
    int hf = tid & 1;
    const __half* gA = A + (size_t)(m0 + r) * K + hf * 16;
    const __half* gW = W + (size_t)(n0 + r) * K + hf * 16;
    uint32_t sdst = sb + r * GROWB + hf * 32;

    float acc[4][4][4];
    #pragma unroll
    for (int mi = 0; mi < 4; ++mi)
        #pragma unroll
        for (int nj = 0; nj < 4; ++nj)
            #pragma unroll
            for (int e = 0; e < 4; ++e) acc[mi][nj][e] = 0.f;

    uint32_t lmo = (uint32_t)((lane & 15) * GROWB + (lane >> 4) * 16);
    int nch = K / 32;

    {
        cp16(sdst + OFF_A, gA);  cp16(sdst + OFF_A + 16, gA + 8);
        cp16(sdst + OFF_W, gW);  cp16(sdst + OFF_W + 16, gW + 8);
        CP_COMMIT();
        CP_WAIT0();
        __syncthreads();
    }

    for (int c = 0; c < nch; ++c) {
        int s = c & 1;
        if (c + 1 < nch) {
            size_t ko = (size_t)(c + 1) * 32;
            uint32_t d2 = sdst + (s ^ 1) * STAGEB;
            cp16(d2 + OFF_A, gA + ko);  cp16(d2 + OFF_A + 16, gA + ko + 8);
            cp16(d2 + OFF_W, gW + ko);  cp16(d2 + OFF_W + 16, gW + ko + 8);
            CP_COMMIT();
        }

        uint32_t stgb = sb + s * STAGEB;
        #pragma unroll
        for (int ks = 0; ks < 2; ++ks) {
            uint32_t kb = ks * 32;
            uint32_t aF[4][4], bW[2][4];
            #pragma unroll
            for (int mi = 0; mi < 4; ++mi) {
                uint32_t ra = (wm + mi * 16) * GROWB + lmo + kb;
                ldsm4(aF[mi], stgb + OFF_A + ra);
            }
            #pragma unroll
            for (int p = 0; p < 2; ++p) {
                uint32_t rb = (wn + p * 16) * GROWB + lmo + kb;
                ldsm4(bW[p], stgb + OFF_W + rb);
            }
            #pragma unroll
            for (int mi = 0; mi < 4; ++mi) {
                #pragma unroll
                for (int nj = 0; nj < 4; ++nj) {
                    uint32_t b0 = bW[nj >> 1][nj & 1];
                    uint32_t b1 = bW[nj >> 1][(nj & 1) + 2];
                    mma16816(acc[mi][nj], aF[mi], b0, b1);
                }
            }
        }

        if (c + 1 < nch) CP_WAIT0();
        __syncthreads();
    }

    int gid  = lane >> 2;
    int tid4 = lane & 3;
    float b2v[4][2];
    #pragma unroll
    for (int nj = 0; nj < 4; ++nj) {
        int col = n0 + wn + nj * 8 + tid4 * 2;
        b2v[nj][0] = bias[col];
        b2v[nj][1] = bias[col + 1];
    }
    #pragma unroll
    for (int mi = 0; mi < 4; ++mi) {
        #pragma unroll
        for (int half = 0; half < 2; ++half) {
            int row = m0 + wm + mi * 16 + gid + half * 8;
            #pragma unroll
            for (int nj = 0; nj < 4; ++nj) {
                int col = n0 + wn + nj * 8 + tid4 * 2;
                float v0 = acc[mi][nj][half * 2 + 0] + b2v[nj][0];
                float v1 = acc[mi][nj][half * 2 + 1] + b2v[nj][1];
                if (EPI == EPI_RES) {
                    float2 rv = *reinterpret_cast<const float2*>(&res[(size_t)row * N + col]);
                    v0 += rv.x; v1 += rv.y;
                    float2 o; o.x = v0; o.y = v1;
                    *reinterpret_cast<float2*>(&Cf[(size_t)row * N + col]) = o;
                } else {
                    if (EPI == EPI_GELUS) { v0 = gelu_exact(v0); v1 = gelu_exact(v1); }
                    *reinterpret_cast<uint32_t*>(&Chi[(size_t)row * N + col]) = pack_hf2(v0, v1);
                }
            }
        }
    }
}

// ---------------- MMA flash attention ---------------------------------------
// grid = (SEQ/128, B*H), 256 threads (8 warps, 16 query rows each).
// All operands single fp16: 1 MMA per position.
#define QST 72                         // smem row stride in fp16 elems (144B)
#define AQ  0
#define AKV0 (128*QST)                 // stage base
#define KVSTG (2*64*QST)               // elems per stage (K, V)
#define AOF_K 0
#define AOF_V (64*QST)
#define ATTN_SMEM ((128*QST + 2*KVSTG) * 2)   // 55296 bytes

__global__ __launch_bounds__(256, 2)
void attn_mma(const __half* __restrict__ Qh, const __half* __restrict__ Kh,
              const __half* __restrict__ Vh, __half* __restrict__ Ohi)
{
    extern __shared__ __half sma[];
    uint32_t sb = smem_to_u32(sma);

    int tid  = threadIdx.x;
    int lane = tid & 31;
    int warp = tid >> 5;
    int bh = blockIdx.y;
    int b = bh >> 4, h = bh & 15;
    int qbase  = b * SEQ + blockIdx.x * 128;
    int kvbase = b * SEQ;
    int hcol   = h * HDIM;
    int wm = warp * 16;

    // ---- load Q (128 rows x 64 cols): 2 threads per row ----
    {
        int rr = tid >> 1, cc2 = (tid & 1) * 4;
        const __half* gq = Qh + (size_t)(qbase + rr) * DMODEL + hcol + cc2 * 8;
        uint32_t dq = sb + (rr * QST + cc2 * 8) * 2;
        #pragma unroll
        for (int c = 0; c < 4; ++c)
            cp16(dq + AQ * 2 + c * 16, gq + c * 8);
    }

    // ---- KV stage loader: 4 threads per row (64 rows per tile) ----
    int krr = tid >> 2;              // 0..63
    int kc4 = (tid & 3) * 16;        // elem offset within 64-col row
    uint32_t kdst = sb + (krr * QST + kc4) * 2;
    size_t kgo = (size_t)hcol + kc4;

    {   // prologue stage 0 (tile 0)
        size_t grow = (size_t)(kvbase + krr) * DMODEL + kgo;
        uint32_t st = kdst + AKV0 * 2;
        cp16(st + AOF_K*2, Kh + grow);  cp16(st + AOF_K*2 + 16, Kh + grow + 8);
        cp16(st + AOF_V*2, Vh + grow);  cp16(st + AOF_V*2 + 16, Vh + grow + 8);
        CP_COMMIT();
        CP_WAIT0();
        __syncthreads();
    }

    float oacc[8][4];
    #pragma unroll
    for (int j = 0; j < 8; ++j)
        #pragma unroll
        for (int e = 0; e < 4; ++e) oacc[j][e] = 0.f;
    float mrow[2] = {-1e30f, -1e30f};
    float lrow[2] = {0.f, 0.f};

    uint32_t lmo = (uint32_t)((lane & 15) * QST * 2 + (lane >> 4) * 16);
    const float scale = 0.125f;

    const int NT = SEQ / 64;
    for (int t = 0; t < NT; ++t) {
        int s = t & 1;
        if (t + 1 < NT) {
            size_t grow = (size_t)(kvbase + (t + 1) * 64 + krr) * DMODEL + kgo;
            uint32_t st = kdst + (AKV0 + (s ^ 1) * KVSTG) * 2;
            cp16(st + AOF_K*2, Kh + grow);  cp16(st + AOF_K*2 + 16, Kh + grow + 8);
            cp16(st + AOF_V*2, Vh + grow);  cp16(st + AOF_V*2 + 16, Vh + grow + 8);
            CP_COMMIT();
        }

        uint32_t kvb = sb + (AKV0 + s * KVSTG) * 2;

        // ---- scores: S[16 x 64] = Q_tile . K_tile^T ----
        float sacc[8][4];
        #pragma unroll
        for (int j = 0; j < 8; ++j)
            #pragma unroll
            for (int e = 0; e < 4; ++e) sacc[j][e] = 0.f;

        #pragma unroll
        for (int kk = 0; kk < 4; ++kk) {
            uint32_t aQ[4], bK[4];
            uint32_t qa = sb + wm * QST * 2 + lmo + kk * 32;
            ldsm4(aQ, qa + AQ * 2);
            #pragma unroll
            for (int p = 0; p < 4; ++p) {
                uint32_t ka = kvb + p * 16 * QST * 2 + lmo + kk * 32;
                ldsm4(bK, ka + AOF_K * 2);
                #pragma unroll
                for (int tt = 0; tt < 2; ++tt) {
                    int j = p * 2 + tt;
                    mma16816(sacc[j], aQ, bK[tt], bK[tt + 2]);
                }
            }
        }

        // ---- online softmax (rows: lane>>2 and +8) ----
        float alpha[2];
        #pragma unroll
        for (int hf = 0; hf < 2; ++hf) {
            float mv = mrow[hf];
            #pragma unroll
            for (int j = 0; j < 8; ++j) {
                sacc[j][2*hf]   *= scale;
                sacc[j][2*hf+1] *= scale;
                mv = fmaxf(mv, fmaxf(sacc[j][2*hf], sacc[j][2*hf+1]));
            }
            mv = fmaxf(mv, __shfl_xor_sync(0xffffffffu, mv, 1));
            mv = fmaxf(mv, __shfl_xor_sync(0xffffffffu, mv, 2));
            alpha[hf] = __expf(mrow[hf] - mv);
            float ls = 0.f;
            #pragma unroll
            for (int j = 0; j < 8; ++j) {
                sacc[j][2*hf]   = __expf(sacc[j][2*hf]   - mv);
                sacc[j][2*hf+1] = __expf(sacc[j][2*hf+1] - mv);
                ls += sacc[j][2*hf] + sacc[j][2*hf+1];
            }
            ls += __shfl_xor_sync(0xffffffffu, ls, 1);
            ls += __shfl_xor_sync(0xffffffffu, ls, 2);
            lrow[hf] = lrow[hf] * alpha[hf] + ls;
            mrow[hf] = mv;
            #pragma unroll
            for (int j = 0; j < 8; ++j) {
                oacc[j][2*hf]   *= alpha[hf];
                oacc[j][2*hf+1] *= alpha[hf];
            }
        }

        // ---- repack P (C-fragment -> A-fragment) ----
        uint32_t pF[4][4];
        #pragma unroll
        for (int kk = 0; kk < 4; ++kk) {
            int j0 = 2 * kk, j1 = 2 * kk + 1;
            pF[kk][0] = pack_hf2(sacc[j0][0], sacc[j0][1]);
            pF[kk][1] = pack_hf2(sacc[j0][2], sacc[j0][3]);
            pF[kk][2] = pack_hf2(sacc[j1][0], sacc[j1][1]);
            pF[kk][3] = pack_hf2(sacc[j1][2], sacc[j1][3]);
        }

        // ---- PV: O += P[16x64] . V[64x64] ----
        #pragma unroll
        for (int kk = 0; kk < 4; ++kk) {
            #pragma unroll
            for (int p = 0; p < 4; ++p) {
                uint32_t va = kvb + kk * 16 * QST * 2 + lmo + p * 32;
                uint32_t vV[4];
                ldsm4t(vV, va + AOF_V * 2);
                #pragma unroll
                for (int tt = 0; tt < 2; ++tt) {
                    int j = p * 2 + tt;
                    mma16816(oacc[j], pF[kk], vV[tt * 2], vV[tt * 2 + 1]);
                }
            }
        }

        if (t + 1 < NT) CP_WAIT0();
        __syncthreads();
    }

    // ---- epilogue ----
    #pragma unroll
    for (int hf = 0; hf < 2; ++hf) {
        float il = 1.0f / lrow[hf];
        int row = qbase + wm + (lane >> 2) + hf * 8;
        #pragma unroll
        for (int j = 0; j < 8; ++j) {
            int col = hcol + j * 8 + (lane & 3) * 2;
            float v0 = oacc[j][2*hf]   * il;
            float v1 = oacc[j][2*hf+1] * il;
            *reinterpret_cast<uint32_t*>(&Ohi[(size_t)row * DMODEL + col]) = pack_hf2(v0, v1);
        }
    }
}

// ---------------- launch ----------------------------------------------------
extern "C" void kernel_launch(void* const* d_in, const int* in_sizes, int n_in,
                              void* d_out, int out_size)
{
    (void)in_sizes; (void)n_in; (void)out_size;
    const float* x    = (const float*)d_in[0];
    const float* wq   = (const float*)d_in[1];
    const float* bq   = (const float*)d_in[2];
    const float* wk   = (const float*)d_in[3];
    const float* bk   = (const float*)d_in[4];
    const float* wv   = (const float*)d_in[5];
    const float* bv   = (const float*)d_in[6];
    const float* wo   = (const float*)d_in[7];
    const float* bo   = (const float*)d_in[8];
    const float* ln1g = (const float*)d_in[9];
    const float* ln1b = (const float*)d_in[10];
    const float* w1   = (const float*)d_in[11];
    const float* b1   = (const float*)d_in[12];
    const float* w2   = (const float*)d_in[13];
    const float* b2   = (const float*)d_in[14];
    const float* ln2g = (const float*)d_in[15];
    const float* ln2b = (const float*)d_in[16];
    float* out = (float*)d_out;

    float *xn, *r1, *y;
    cudaGetSymbolAddress((void**)&xn, g_xn);
    cudaGetSymbolAddress((void**)&r1, g_r1);
    cudaGetSymbolAddress((void**)&y,  g_y);

    __half *xnh,*yh,*qh,*kh,*vh,*ath,*hh;
    __half *wqh,*wkh,*wvh,*woh,*w1h,*w2h;
    cudaGetSymbolAddress((void**)&xnh, g_xnh);
    cudaGetSymbolAddress((void**)&yh,  g_yh);
    cudaGetSymbolAddress((void**)&qh,  g_qh);
    cudaGetSymbolAddress((void**)&kh,  g_kh);
    cudaGetSymbolAddress((void**)&vh,  g_vh);
    cudaGetSymbolAddress((void**)&ath, g_ath);
    cudaGetSymbolAddress((void**)&hh,  g_hh);
    cudaGetSymbolAddress((void**)&wqh, g_wqh); cudaGetSymbolAddress((void**)&wkh, g_wkh);
    cudaGetSymbolAddress((void**)&wvh, g_wvh); cudaGetSymbolAddress((void**)&woh, g_woh);
    cudaGetSymbolAddress((void**)&w1h, g_w1h); cudaGetSymbolAddress((void**)&w2h, g_w2h);

    cudaFuncSetAttribute(attn_mma, cudaFuncAttributeMaxDynamicSharedMemorySize, ATTN_SMEM);
    cudaFuncSetAttribute(gemm_mma<EPI_SINGLE>, cudaFuncAttributeMaxDynamicSharedMemorySize, GEMM_SMEM);
    cudaFuncSetAttribute(gemm_mma<EPI_RES>,    cudaFuncAttributeMaxDynamicSharedMemorySize, GEMM_SMEM);
    cudaFuncSetAttribute(gemm_mma<EPI_GELUS>,  cudaFuncAttributeMaxDynamicSharedMemorySize, GEMM_SMEM);

    int nDD4 = DMODEL*DMODEL/4, nFD4 = FFDIM*DMODEL/4;
    conv_kernel<<<(nDD4+255)/256, 256>>>(wq, wqh, nDD4);
    conv_kernel<<<(nDD4+255)/256, 256>>>(wk, wkh, nDD4);
    conv_kernel<<<(nDD4+255)/256, 256>>>(wv, wvh, nDD4);
    conv_kernel<<<(nDD4+255)/256, 256>>>(wo, woh, nDD4);
    conv_kernel<<<(nFD4+255)/256, 256>>>(w1, w1h, nFD4);
    conv_kernel<<<(nFD4+255)/256, 256>>>(w2, w2h, nFD4);

    dim3 gD(DMODEL/128, MROWS/128);
    dim3 gF(FFDIM/128,  MROWS/128);

    ln_conv_kernel<<<MROWS, 256>>>(x, ln1g, ln1b, xn, xnh);
    gemm_mma<EPI_SINGLE><<<gD, 256, GEMM_SMEM>>>(xnh, wqh, bq, nullptr, nullptr, qh, MROWS, DMODEL, DMODEL);
    gemm_mma<EPI_SINGLE><<<gD, 256, GEMM_SMEM>>>(xnh, wkh, bk, nullptr, nullptr, kh, MROWS, DMODEL, DMODEL);
    gemm_mma<EPI_SINGLE><<<gD, 256, GEMM_SMEM>>>(xnh, wvh, bv, nullptr, nullptr, vh, MROWS, DMODEL, DMODEL);
    attn_mma<<<dim3(SEQ/128, BATCH*NHEAD), 256, ATTN_SMEM>>>(qh, kh, vh, ath);
    gemm_mma<EPI_RES><<<gD, 256, GEMM_SMEM>>>(ath, woh, bo, xn, r1, nullptr, MROWS, DMODEL, DMODEL);
    ln_conv_kernel<<<MROWS, 256>>>(r1, ln2g, ln2b, y, yh);
    gemm_mma<EPI_GELUS><<<gF, 256, GEMM_SMEM>>>(yh, w1h, b1, nullptr, nullptr, hh, MROWS, FFDIM, DMODEL);
    gemm_mma<EPI_RES><<<gD, 256, GEMM_SMEM>>>(hh, w2h, b2, y, out, nullptr, MROWS, DMODEL, FFDIM);
}

// round 10
// speedup vs baseline: 15.5326x; 1.0223x over previous
#include <cuda_runtime.h>
#include <cuda_fp16.h>
#include <math.h>
#include <stdint.h>

// Problem constants
#define BATCH 2
#define SEQ   2048
#define DMODEL 1024
#define NHEAD 16
#define HDIM  64
#define FFDIM 4096
#define MROWS (BATCH*SEQ)   // 4096
#define LN_EPS 1e-5f

// ---------------- scratch buffers ------------------------------------------
__device__ float g_xn [MROWS*DMODEL];
__device__ float g_r1 [MROWS*DMODEL];
__device__ float g_y  [MROWS*DMODEL];

__device__ __half g_xnh[MROWS*DMODEL];
__device__ __half g_yh [MROWS*DMODEL];
__device__ __half g_qh [MROWS*DMODEL];
__device__ __half g_kh [MROWS*DMODEL];
__device__ __half g_vh [MROWS*DMODEL];
__device__ __half g_ath[MROWS*DMODEL];
__device__ __half g_hh [MROWS*FFDIM];

__device__ __half g_wqkvh[3*DMODEL*DMODEL];   // concat q,k,v weights
__device__ float  g_bqkv [3*DMODEL];          // concat q,k,v biases
__device__ __half g_woh[DMODEL*DMODEL];
__device__ __half g_w1h[FFDIM*DMODEL];
__device__ __half g_w2h[DMODEL*FFDIM];

// ---------------- helpers ---------------------------------------------------
__device__ __forceinline__ uint32_t smem_to_u32(const void* p) {
    uint32_t a;
    asm("{ .reg .u64 t; cvta.to.shared.u64 t, %1; cvt.u32.u64 %0, t; }"
        : "=r"(a) : "l"(p));
    return a;
}
__device__ __forceinline__ void cp16(uint32_t d, const void* s) {
    asm volatile("cp.async.cg.shared.global [%0], [%1], 16;" :: "r"(d), "l"(s) : "memory");
}
#define CP_COMMIT() asm volatile("cp.async.commit_group;" ::: "memory")
#define CP_WAIT0()  asm volatile("cp.async.wait_group 0;" ::: "memory")

__device__ __forceinline__ void ldsm4(uint32_t* r, uint32_t addr) {
    asm volatile("ldmatrix.sync.aligned.m8n8.x4.shared.b16 {%0,%1,%2,%3}, [%4];"
        : "=r"(r[0]), "=r"(r[1]), "=r"(r[2]), "=r"(r[3]) : "r"(addr));
}
__device__ __forceinline__ void ldsm4t(uint32_t* r, uint32_t addr) {
    asm volatile("ldmatrix.sync.aligned.m8n8.x4.trans.shared.b16 {%0,%1,%2,%3}, [%4];"
        : "=r"(r[0]), "=r"(r[1]), "=r"(r[2]), "=r"(r[3]) : "r"(addr));
}
__device__ __forceinline__ void mma16816(float* c, const uint32_t* a,
                                         uint32_t b0, uint32_t b1) {
    asm volatile("mma.sync.aligned.m16n8k16.row.col.f32.f16.f16.f32 "
        "{%0,%1,%2,%3}, {%4,%5,%6,%7}, {%8,%9}, {%0,%1,%2,%3};"
        : "+f"(c[0]), "+f"(c[1]), "+f"(c[2]), "+f"(c[3])
        : "r"(a[0]), "r"(a[1]), "r"(a[2]), "r"(a[3]), "r"(b0), "r"(b1));
}

__device__ __forceinline__ uint32_t pack_hf2(float a, float b) {
    __half2 t;
    t.x = __float2half_rn(a);
    t.y = __float2half_rn(b);
    uint32_t u;
    *reinterpret_cast<__half2*>(&u) = t;
    return u;
}
__device__ __forceinline__ float gelu_exact(float v) {
    return 0.5f * v * (1.0f + erff(v * 0.70710678118654752440f));
}

// ---------------- fused weight converts --------------------------------------
// QKV: convert wq/wk/wv into the concat buffer, plus concat biases.
#define DD4 (DMODEL*DMODEL/4)
__global__ __launch_bounds__(256)
void conv_qkv_kernel(const float* __restrict__ wq, const float* __restrict__ wk,
                     const float* __restrict__ wv, const float* __restrict__ bq,
                     const float* __restrict__ bk, const float* __restrict__ bv,
                     __half* __restrict__ dst, float* __restrict__ bdst)
{
    int i = blockIdx.x * blockDim.x + threadIdx.x;
    if (i < 3 * DMODEL / 4) {   // bias concat (3072 floats = 768 float4)
        int seg = i / (DMODEL/4), li = i % (DMODEL/4);
        const float* src = (seg == 0) ? bq : (seg == 1) ? bk : bv;
        reinterpret_cast<float4*>(bdst)[i] = reinterpret_cast<const float4*>(src)[li];
    }
    if (i >= 3 * DD4) return;
    int seg = i / DD4, li = i % DD4;
    const float* src = (seg == 0) ? wq : (seg == 1) ? wk : wv;
    float4 v = reinterpret_cast<const float4*>(src)[li];
    uint2 hu;
    hu.x = pack_hf2(v.x, v.y);
    hu.y = pack_hf2(v.z, v.w);
    reinterpret_cast<uint2*>(dst)[i] = hu;
}

// wo + w1 + w2 in one launch
#define FD4 (FFDIM*DMODEL/4)
__global__ __launch_bounds__(256)
void conv_rest_kernel(const float* __restrict__ wo, const float* __restrict__ w1,
                      const float* __restrict__ w2, __half* __restrict__ oh,
                      __half* __restrict__ h1, __half* __restrict__ h2)
{
    int i = blockIdx.x * blockDim.x + threadIdx.x;
    if (i >= DD4 + 2 * FD4) return;
    const float* src; __half* dst; int li;
    if (i < DD4)            { src = w1 ? wo : wo; dst = oh; li = i; src = wo; }
    else if (i < DD4 + FD4) { src = w1; dst = h1; li = i - DD4; }
    else                    { src = w2; dst = h2; li = i - DD4 - FD4; }
    float4 v = reinterpret_cast<const float4*>(src)[li];
    uint2 hu;
    hu.x = pack_hf2(v.x, v.y);
    hu.y = pack_hf2(v.z, v.w);
    reinterpret_cast<uint2*>(dst)[li] = hu;
}

// ---------------- LayerNorm + fp16 out ---------------------------------------
__global__ __launch_bounds__(256)
void ln_conv_kernel(const float* __restrict__ x, const float* __restrict__ g,
                    const float* __restrict__ b, float* __restrict__ y,
                    __half* __restrict__ yh)
{
    int row = blockIdx.x;
    int tid = threadIdx.x;
    const float4* xr = reinterpret_cast<const float4*>(x + (size_t)row * DMODEL);
    float4 v = xr[tid];

    float s = v.x + v.y + v.z + v.w;
    float q = v.x*v.x + v.y*v.y + v.z*v.z + v.w*v.w;
    #pragma unroll
    for (int o = 16; o > 0; o >>= 1) {
        s += __shfl_down_sync(0xffffffffu, s, o);
        q += __shfl_down_sync(0xffffffffu, q, o);
    }
    __shared__ float ss[8], sq[8];
    int wid = tid >> 5, lane = tid & 31;
    if (lane == 0) { ss[wid] = s; sq[wid] = q; }
    __syncthreads();
    float tot = 0.f, totq = 0.f;
    #pragma unroll
    for (int i = 0; i < 8; ++i) { tot += ss[i]; totq += sq[i]; }

    float mu  = tot * (1.0f / DMODEL);
    float var = totq * (1.0f / DMODEL) - mu * mu;
    float rs  = rsqrtf(var + LN_EPS);

    float4 gg = reinterpret_cast<const float4*>(g)[tid];
    float4 bb = reinterpret_cast<const float4*>(b)[tid];
    float4 o;
    o.x = (v.x - mu) * rs * gg.x + bb.x;
    o.y = (v.y - mu) * rs * gg.y + bb.y;
    o.z = (v.z - mu) * rs * gg.z + bb.z;
    o.w = (v.w - mu) * rs * gg.w + bb.w;
    reinterpret_cast<float4*>(y + (size_t)row * DMODEL)[tid] = o;

    uint2 hu;
    hu.x = pack_hf2(o.x, o.y);
    hu.y = pack_hf2(o.z, o.w);
    reinterpret_cast<uint2*>(yh + (size_t)row * DMODEL)[tid] = hu;
}

// ---------------- warp-MMA GEMM ---------------------------------------------
// C[M,N] = A[M,K] @ W[N,K]^T  (fp16, 1 MMA per position)
#define EPI_RES    1
#define EPI_GELUS  2
#define EPI_QKV3   5

#define GROWB  80
#define MATB   (128 * GROWB)
#define OFF_A  0
#define OFF_W  MATB
#define STAGEB (2*MATB)        // 20480
#define GEMM_SMEM (2*STAGEB)   // 40960

template<int EPI>
__global__ __launch_bounds__(256, 2)
void gemm_mma(const __half* __restrict__ A, const __half* __restrict__ W,
              const float* __restrict__ bias, const float* __restrict__ res,
              float* __restrict__ Cf, __half* __restrict__ Chi,
              __half* __restrict__ C2, __half* __restrict__ C3,
              int M, int N, int K)
{
    extern __shared__ char smc[];
    uint32_t sb = smem_to_u32(smc);
    int tid  = threadIdx.x;
    int lane = tid & 31;
    int warp = tid >> 5;
    int n0 = blockIdx.x * 128;
    int m0 = blockIdx.y * 128;
    int wm = (warp >> 2) * 64;
    int wn = (warp & 3) * 32;

    int r  = tid >> 1;
    int hf = tid & 1;
    const __half* gA = A + (size_t)(m0 + r) * K + hf * 16;
    const __half* gW = W + (size_t)(n0 + r) * K + hf * 16;
    uint32_t sdst = sb + r * GROWB + hf * 32;

    float acc[4][4][4];
    #pragma unroll
    for (int mi = 0; mi < 4; ++mi)
        #pragma unroll
        for (int nj = 0; nj < 4; ++nj)
            #pragma unroll
            for (int e = 0; e < 4; ++e) acc[mi][nj][e] = 0.f;

    uint32_t lmo = (uint32_t)((lane & 15) * GROWB + (lane >> 4) * 16);
    int nch = K / 32;

    {
        cp16(sdst + OFF_A, gA);  cp16(sdst + OFF_A + 16, gA + 8);
        cp16(sdst + OFF_W, gW);  cp16(sdst + OFF_W + 16, gW + 8);
        CP_COMMIT();
        CP_WAIT0();
        __syncthreads();
    }

    for (int c = 0; c < nch; ++c) {
        int s = c & 1;
        if (c + 1 < nch) {
            size_t ko = (size_t)(c + 1) * 32;
            uint32_t d2 = sdst + (s ^ 1) * STAGEB;
            cp16(d2 + OFF_A, gA + ko);  cp16(d2 + OFF_A + 16, gA + ko + 8);
            cp16(d2 + OFF_W, gW + ko);  cp16(d2 + OFF_W + 16, gW + ko + 8);
            CP_COMMIT();
        }

        uint32_t stgb = sb + s * STAGEB;
        #pragma unroll
        for (int ks = 0; ks < 2; ++ks) {
            uint32_t kb = ks * 32;
            uint32_t aF[4][4], bW[2][4];
            #pragma unroll
            for (int mi = 0; mi < 4; ++mi) {
                uint32_t ra = (wm + mi * 16) * GROWB + lmo + kb;
                ldsm4(aF[mi], stgb + OFF_A + ra);
            }
            #pragma unroll
            for (int p = 0; p < 2; ++p) {
                uint32_t rb = (wn + p * 16) * GROWB + lmo + kb;
                ldsm4(bW[p], stgb + OFF_W + rb);
            }
            #pragma unroll
            for (int mi = 0; mi < 4; ++mi) {
                #pragma unroll
                for (int nj = 0; nj < 4; ++nj) {
                    uint32_t b0 = bW[nj >> 1][nj & 1];
                    uint32_t b1 = bW[nj >> 1][(nj & 1) + 2];
                    mma16816(acc[mi][nj], aF[mi], b0, b1);
                }
            }
        }

        if (c + 1 < nch) CP_WAIT0();
        __syncthreads();
    }

    int gid  = lane >> 2;
    int tid4 = lane & 3;
    float b2v[4][2];
    #pragma unroll
    for (int nj = 0; nj < 4; ++nj) {
        int col = n0 + wn + nj * 8 + tid4 * 2;
        b2v[nj][0] = bias[col];
        b2v[nj][1] = bias[col + 1];
    }
    // QKV3 destination select (whole CTA column range in one buffer)
    __half* qdst = Chi;
    if (EPI == EPI_QKV3) {
        qdst = (n0 < DMODEL) ? Chi : ((n0 < 2*DMODEL) ? C2 : C3);
    }
    #pragma unroll
    for (int mi = 0; mi < 4; ++mi) {
        #pragma unroll
        for (int half = 0; half < 2; ++half) {
            int row = m0 + wm + mi * 16 + gid + half * 8;
            #pragma unroll
            for (int nj = 0; nj < 4; ++nj) {
                int col = n0 + wn + nj * 8 + tid4 * 2;
                float v0 = acc[mi][nj][half * 2 + 0] + b2v[nj][0];
                float v1 = acc[mi][nj][half * 2 + 1] + b2v[nj][1];
                if (EPI == EPI_RES) {
                    float2 rv = *reinterpret_cast<const float2*>(&res[(size_t)row * N + col]);
                    v0 += rv.x; v1 += rv.y;
                    float2 o; o.x = v0; o.y = v1;
                    *reinterpret_cast<float2*>(&Cf[(size_t)row * N + col]) = o;
                } else if (EPI == EPI_QKV3) {
                    int lcol = col & (DMODEL - 1);
                    *reinterpret_cast<uint32_t*>(&qdst[(size_t)row * DMODEL + lcol]) = pack_hf2(v0, v1);
                } else {
                    if (EPI == EPI_GELUS) { v0 = gelu_exact(v0); v1 = gelu_exact(v1); }
                    *reinterpret_cast<uint32_t*>(&Chi[(size_t)row * N + col]) = pack_hf2(v0, v1);
                }
            }
        }
    }
}

// ---------------- MMA flash attention ---------------------------------------
#define QST 72                         // smem row stride in fp16 elems (144B)
#define AQ  0
#define AKV0 (128*QST)                 // stage base
#define KVSTG (2*64*QST)               // elems per stage (K, V)
#define AOF_K 0
#define AOF_V (64*QST)
#define ATTN_SMEM ((128*QST + 2*KVSTG) * 2)   // 55296 bytes

__global__ __launch_bounds__(256, 2)
void attn_mma(const __half* __restrict__ Qh, const __half* __restrict__ Kh,
              const __half* __restrict__ Vh, __half* __restrict__ Ohi)
{
    extern __shared__ __half sma[];
    uint32_t sb = smem_to_u32(sma);

    int tid  = threadIdx.x;
    int lane = tid & 31;
    int warp = tid >> 5;
    int bh = blockIdx.y;
    int b = bh >> 4, h = bh & 15;
    int qbase  = b * SEQ + blockIdx.x * 128;
    int kvbase = b * SEQ;
    int hcol   = h * HDIM;
    int wm = warp * 16;

    // ---- load Q (128 rows x 64 cols): 2 threads per row ----
    {
        int rr = tid >> 1, cc2 = (tid & 1) * 4;
        const __half* gq = Qh + (size_t)(qbase + rr) * DMODEL + hcol + cc2 * 8;
        uint32_t dq = sb + (rr * QST + cc2 * 8) * 2;
        #pragma unroll
        for (int c = 0; c < 4; ++c)
            cp16(dq + AQ * 2 + c * 16, gq + c * 8);
    }

    // ---- KV stage loader: 4 threads per row (64 rows per tile) ----
    int krr = tid >> 2;
    int kc4 = (tid & 3) * 16;
    uint32_t kdst = sb + (krr * QST + kc4) * 2;
    size_t kgo = (size_t)hcol + kc4;

    {
        size_t grow = (size_t)(kvbase + krr) * DMODEL + kgo;
        uint32_t st = kdst + AKV0 * 2;
        cp16(st + AOF_K*2, Kh + grow);  cp16(st + AOF_K*2 + 16, Kh + grow + 8);
        cp16(st + AOF_V*2, Vh + grow);  cp16(st + AOF_V*2 + 16, Vh + grow + 8);
        CP_COMMIT();
        CP_WAIT0();
        __syncthreads();
    }

    float oacc[8][4];
    #pragma unroll
    for (int j = 0; j < 8; ++j)
        #pragma unroll
        for (int e = 0; e < 4; ++e) oacc[j][e] = 0.f;
    float mrow[2] = {-1e30f, -1e30f};
    float lrow[2] = {0.f, 0.f};

    uint32_t lmo = (uint32_t)((lane & 15) * QST * 2 + (lane >> 4) * 16);
    const float scale = 0.125f;

    const int NT = SEQ / 64;
    for (int t = 0; t < NT; ++t) {
        int s = t & 1;
        if (t + 1 < NT) {
            size_t grow = (size_t)(kvbase + (t + 1) * 64 + krr) * DMODEL + kgo;
            uint32_t st = kdst + (AKV0 + (s ^ 1) * KVSTG) * 2;
            cp16(st + AOF_K*2, Kh + grow);  cp16(st + AOF_K*2 + 16, Kh + grow + 8);
            cp16(st + AOF_V*2, Vh + grow);  cp16(st + AOF_V*2 + 16, Vh + grow + 8);
            CP_COMMIT();
        }

        uint32_t kvb = sb + (AKV0 + s * KVSTG) * 2;

        float sacc[8][4];
        #pragma unroll
        for (int j = 0; j < 8; ++j)
            #pragma unroll
            for (int e = 0; e < 4; ++e) sacc[j][e] = 0.f;

        #pragma unroll
        for (int kk = 0; kk < 4; ++kk) {
            uint32_t aQ[4], bK[4];
            uint32_t qa = sb + wm * QST * 2 + lmo + kk * 32;
            ldsm4(aQ, qa + AQ * 2);
            #pragma unroll
            for (int p = 0; p < 4; ++p) {
                uint32_t ka = kvb + p * 16 * QST * 2 + lmo + kk * 32;
                ldsm4(bK, ka + AOF_K * 2);
                #pragma unroll
                for (int tt = 0; tt < 2; ++tt) {
                    int j = p * 2 + tt;
                    mma16816(sacc[j], aQ, bK[tt], bK[tt + 2]);
                }
            }
        }

        float alpha[2];
        #pragma unroll
        for (int hf = 0; hf < 2; ++hf) {
            float mv = mrow[hf];
            #pragma unroll
            for (int j = 0; j < 8; ++j) {
                sacc[j][2*hf]   *= scale;
                sacc[j][2*hf+1] *= scale;
                mv = fmaxf(mv, fmaxf(sacc[j][2*hf], sacc[j][2*hf+1]));
            }
            mv = fmaxf(mv, __shfl_xor_sync(0xffffffffu, mv, 1));
            mv = fmaxf(mv, __shfl_xor_sync(0xffffffffu, mv, 2));
            alpha[hf] = __expf(mrow[hf] - mv);
            float ls = 0.f;
            #pragma unroll
            for (int j = 0; j < 8; ++j) {
                sacc[j][2*hf]   = __expf(sacc[j][2*hf]   - mv);
                sacc[j][2*hf+1] = __expf(sacc[j][2*hf+1] - mv);
                ls += sacc[j][2*hf] + sacc[j][2*hf+1];
            }
            ls += __shfl_xor_sync(0xffffffffu, ls, 1);
            ls += __shfl_xor_sync(0xffffffffu, ls, 2);
            lrow[hf] = lrow[hf] * alpha[hf] + ls;
            mrow[hf] = mv;
            #pragma unroll
            for (int j = 0; j < 8; ++j) {
                oacc[j][2*hf]   *= alpha[hf];
                oacc[j][2*hf+1] *= alpha[hf];
            }
        }

        uint32_t pF[4][4];
        #pragma unroll
        for (int kk = 0; kk < 4; ++kk) {
            int j0 = 2 * kk, j1 = 2 * kk + 1;
            pF[kk][0] = pack_hf2(sacc[j0][0], sacc[j0][1]);
            pF[kk][1] = pack_hf2(sacc[j0][2], sacc[j0][3]);
            pF[kk][2] = pack_hf2(sacc[j1][0], sacc[j1][1]);
            pF[kk][3] = pack_hf2(sacc[j1][2], sacc[j1][3]);
        }

        #pragma unroll
        for (int kk = 0; kk < 4; ++kk) {
            #pragma unroll
            for (int p = 0; p < 4; ++p) {
                uint32_t va = kvb + kk * 16 * QST * 2 + lmo + p * 32;
                uint32_t vV[4];
                ldsm4t(vV, va + AOF_V * 2);
                #pragma unroll
                for (int tt = 0; tt < 2; ++tt) {
                    int j = p * 2 + tt;
                    mma16816(oacc[j], pF[kk], vV[tt * 2], vV[tt * 2 + 1]);
                }
            }
        }

        if (t + 1 < NT) CP_WAIT0();
        __syncthreads();
    }

    #pragma unroll
    for (int hf = 0; hf < 2; ++hf) {
        float il = 1.0f / lrow[hf];
        int row = qbase + wm + (lane >> 2) + hf * 8;
        #pragma unroll
        for (int j = 0; j < 8; ++j) {
            int col = hcol + j * 8 + (lane & 3) * 2;
            float v0 = oacc[j][2*hf]   * il;
            float v1 = oacc[j][2*hf+1] * il;
            *reinterpret_cast<uint32_t*>(&Ohi[(size_t)row * DMODEL + col]) = pack_hf2(v0, v1);
        }
    }
}

// ---------------- launch ----------------------------------------------------
extern "C" void kernel_launch(void* const* d_in, const int* in_sizes, int n_in,
                              void* d_out, int out_size)
{
    (void)in_sizes; (void)n_in; (void)out_size;
    const float* x    = (const float*)d_in[0];
    const float* wq   = (const float*)d_in[1];
    const float* bq   = (const float*)d_in[2];
    const float* wk   = (const float*)d_in[3];
    const float* bk   = (const float*)d_in[4];
    const float* wv   = (const float*)d_in[5];
    const float* bv   = (const float*)d_in[6];
    const float* wo   = (const float*)d_in[7];
    const float* bo   = (const float*)d_in[8];
    const float* ln1g = (const float*)d_in[9];
    const float* ln1b = (const float*)d_in[10];
    const float* w1   = (const float*)d_in[11];
    const float* b1   = (const float*)d_in[12];
    const float* w2   = (const float*)d_in[13];
    const float* b2   = (const float*)d_in[14];
    const float* ln2g = (const float*)d_in[15];
    const float* ln2b = (const float*)d_in[16];
    float* out = (float*)d_out;

    float *xn, *r1, *y, *bqkv;
    cudaGetSymbolAddress((void**)&xn, g_xn);
    cudaGetSymbolAddress((void**)&r1, g_r1);
    cudaGetSymbolAddress((void**)&y,  g_y);
    cudaGetSymbolAddress((void**)&bqkv, g_bqkv);

    __half *xnh,*yh,*qh,*kh,*vh,*ath,*hh;
    __half *wqkvh,*woh,*w1h,*w2h;
    cudaGetSymbolAddress((void**)&xnh, g_xnh);
    cudaGetSymbolAddress((void**)&yh,  g_yh);
    cudaGetSymbolAddress((void**)&qh,  g_qh);
    cudaGetSymbolAddress((void**)&kh,  g_kh);
    cudaGetSymbolAddress((void**)&vh,  g_vh);
    cudaGetSymbolAddress((void**)&ath, g_ath);
    cudaGetSymbolAddress((void**)&hh,  g_hh);
    cudaGetSymbolAddress((void**)&wqkvh, g_wqkvh);
    cudaGetSymbolAddress((void**)&woh, g_woh);
    cudaGetSymbolAddress((void**)&w1h, g_w1h);
    cudaGetSymbolAddress((void**)&w2h, g_w2h);

    cudaFuncSetAttribute(attn_mma, cudaFuncAttributeMaxDynamicSharedMemorySize, ATTN_SMEM);
    cudaFuncSetAttribute(gemm_mma<EPI_QKV3>,  cudaFuncAttributeMaxDynamicSharedMemorySize, GEMM_SMEM);
    cudaFuncSetAttribute(gemm_mma<EPI_RES>,   cudaFuncAttributeMaxDynamicSharedMemorySize, GEMM_SMEM);
    cudaFuncSetAttribute(gemm_mma<EPI_GELUS>, cudaFuncAttributeMaxDynamicSharedMemorySize, GEMM_SMEM);

    // fused weight converts
    conv_qkv_kernel<<<(3*DD4 + 255)/256, 256>>>(wq, wk, wv, bq, bk, bv, wqkvh, bqkv);
    conv_rest_kernel<<<(DD4 + 2*FD4 + 255)/256, 256>>>(wo, w1, w2, woh, w1h, w2h);

    dim3 gQKV(3*DMODEL/128, MROWS/128);   // 24 x 32
    dim3 gD(DMODEL/128, MROWS/128);       // 8 x 32
    dim3 gF(FFDIM/128,  MROWS/128);       // 32 x 32

    ln_conv_kernel<<<MROWS, 256>>>(x, ln1g, ln1b, xn, xnh);
    gemm_mma<EPI_QKV3><<<gQKV, 256, GEMM_SMEM>>>(xnh, wqkvh, bqkv, nullptr, nullptr, qh, kh, vh, MROWS, 3*DMODEL, DMODEL);
    attn_mma<<<dim3(SEQ/128, BATCH*NHEAD), 256, ATTN_SMEM>>>(qh, kh, vh, ath);
    gemm_mma<EPI_RES><<<gD, 256, GEMM_SMEM>>>(ath, woh, bo, xn, r1, nullptr, nullptr, nullptr, MROWS, DMODEL, DMODEL);
    ln_conv_kernel<<<MROWS, 256>>>(r1, ln2g, ln2b, y, yh);
    gemm_mma<EPI_GELUS><<<gF, 256, GEMM_SMEM>>>(yh, w1h, b1, nullptr, nullptr, hh, nullptr, nullptr, MROWS, FFDIM, DMODEL);
    gemm_mma<EPI_RES><<<gD, 256, GEMM_SMEM>>>(hh, w2h, b2, y, out, nullptr, nullptr, nullptr, MROWS, DMODEL, FFDIM);
}

// round 11
// speedup vs baseline: 16.5028x; 1.0625x over previous
#include <cuda_runtime.h>
#include <cuda_fp16.h>
#include <math.h>
#include <stdint.h>

// Problem constants
#define BATCH 2
#define SEQ   2048
#define DMODEL 1024
#define NHEAD 16
#define HDIM  64
#define FFDIM 4096
#define MROWS (BATCH*SEQ)   // 4096
#define LN_EPS 1e-5f

// ---------------- scratch buffers ------------------------------------------
__device__ float g_xn [MROWS*DMODEL];
__device__ float g_r1 [MROWS*DMODEL];
__device__ float g_y  [MROWS*DMODEL];

__device__ __half g_xnh[MROWS*DMODEL];
__device__ __half g_yh [MROWS*DMODEL];
__device__ __half g_qh [MROWS*DMODEL];
__device__ __half g_kh [MROWS*DMODEL];
__device__ __half g_vh [MROWS*DMODEL];
__device__ __half g_ath[MROWS*DMODEL];
__device__ __half g_hh [MROWS*FFDIM];

__device__ __half g_wqkvh[3*DMODEL*DMODEL];   // concat q,k,v weights
__device__ float  g_bqkv [3*DMODEL];          // concat q,k,v biases
__device__ __half g_woh[DMODEL*DMODEL];
__device__ __half g_w1h[FFDIM*DMODEL];
__device__ __half g_w2h[DMODEL*FFDIM];

// ---------------- helpers ---------------------------------------------------
__device__ __forceinline__ uint32_t smem_to_u32(const void* p) {
    uint32_t a;
    asm("{ .reg .u64 t; cvta.to.shared.u64 t, %1; cvt.u32.u64 %0, t; }"
        : "=r"(a) : "l"(p));
    return a;
}
__device__ __forceinline__ void cp16(uint32_t d, const void* s) {
    asm volatile("cp.async.cg.shared.global [%0], [%1], 16;" :: "r"(d), "l"(s) : "memory");
}
#define CP_COMMIT() asm volatile("cp.async.commit_group;" ::: "memory")
#define CP_WAIT0()  asm volatile("cp.async.wait_group 0;" ::: "memory")
#define CP_WAIT1()  asm volatile("cp.async.wait_group 1;" ::: "memory")

__device__ __forceinline__ void ldsm4(uint32_t* r, uint32_t addr) {
    asm volatile("ldmatrix.sync.aligned.m8n8.x4.shared.b16 {%0,%1,%2,%3}, [%4];"
        : "=r"(r[0]), "=r"(r[1]), "=r"(r[2]), "=r"(r[3]) : "r"(addr));
}
__device__ __forceinline__ void ldsm4t(uint32_t* r, uint32_t addr) {
    asm volatile("ldmatrix.sync.aligned.m8n8.x4.trans.shared.b16 {%0,%1,%2,%3}, [%4];"
        : "=r"(r[0]), "=r"(r[1]), "=r"(r[2]), "=r"(r[3]) : "r"(addr));
}
__device__ __forceinline__ void mma16816(float* c, const uint32_t* a,
                                         uint32_t b0, uint32_t b1) {
    asm volatile("mma.sync.aligned.m16n8k16.row.col.f32.f16.f16.f32 "
        "{%0,%1,%2,%3}, {%4,%5,%6,%7}, {%8,%9}, {%0,%1,%2,%3};"
        : "+f"(c[0]), "+f"(c[1]), "+f"(c[2]), "+f"(c[3])
        : "r"(a[0]), "r"(a[1]), "r"(a[2]), "r"(a[3]), "r"(b0), "r"(b1));
}

__device__ __forceinline__ uint32_t pack_hf2(float a, float b) {
    __half2 t;
    t.x = __float2half_rn(a);
    t.y = __float2half_rn(b);
    uint32_t u;
    *reinterpret_cast<__half2*>(&u) = t;
    return u;
}
__device__ __forceinline__ float gelu_exact(float v) {
    return 0.5f * v * (1.0f + erff(v * 0.70710678118654752440f));
}

// ---------------- fused weight converts --------------------------------------
#define DD4 (DMODEL*DMODEL/4)
__global__ __launch_bounds__(256)
void conv_qkv_kernel(const float* __restrict__ wq, const float* __restrict__ wk,
                     const float* __restrict__ wv, const float* __restrict__ bq,
                     const float* __restrict__ bk, const float* __restrict__ bv,
                     __half* __restrict__ dst, float* __restrict__ bdst)
{
    int i = blockIdx.x * blockDim.x + threadIdx.x;
    if (i < 3 * DMODEL / 4) {
        int seg = i / (DMODEL/4), li = i % (DMODEL/4);
        const float* src = (seg == 0) ? bq : (seg == 1) ? bk : bv;
        reinterpret_cast<float4*>(bdst)[i] = reinterpret_cast<const float4*>(src)[li];
    }
    if (i >= 3 * DD4) return;
    int seg = i / DD4, li = i % DD4;
    const float* src = (seg == 0) ? wq : (seg == 1) ? wk : wv;
    float4 v = reinterpret_cast<const float4*>(src)[li];
    uint2 hu;
    hu.x = pack_hf2(v.x, v.y);
    hu.y = pack_hf2(v.z, v.w);
    reinterpret_cast<uint2*>(dst)[i] = hu;
}

#define FD4 (FFDIM*DMODEL/4)
__global__ __launch_bounds__(256)
void conv_rest_kernel(const float* __restrict__ wo, const float* __restrict__ w1,
                      const float* __restrict__ w2, __half* __restrict__ oh,
                      __half* __restrict__ h1, __half* __restrict__ h2)
{
    int i = blockIdx.x * blockDim.x + threadIdx.x;
    if (i >= DD4 + 2 * FD4) return;
    const float* src; __half* dst; int li;
    if (i < DD4)            { src = wo; dst = oh; li = i; }
    else if (i < DD4 + FD4) { src = w1; dst = h1; li = i - DD4; }
    else                    { src = w2; dst = h2; li = i - DD4 - FD4; }
    float4 v = reinterpret_cast<const float4*>(src)[li];
    uint2 hu;
    hu.x = pack_hf2(v.x, v.y);
    hu.y = pack_hf2(v.z, v.w);
    reinterpret_cast<uint2*>(dst)[li] = hu;
}

// ---------------- LayerNorm + fp16 out ---------------------------------------
__global__ __launch_bounds__(256)
void ln_conv_kernel(const float* __restrict__ x, const float* __restrict__ g,
                    const float* __restrict__ b, float* __restrict__ y,
                    __half* __restrict__ yh)
{
    int row = blockIdx.x;
    int tid = threadIdx.x;
    const float4* xr = reinterpret_cast<const float4*>(x + (size_t)row * DMODEL);
    float4 v = xr[tid];

    float s = v.x + v.y + v.z + v.w;
    float q = v.x*v.x + v.y*v.y + v.z*v.z + v.w*v.w;
    #pragma unroll
    for (int o = 16; o > 0; o >>= 1) {
        s += __shfl_down_sync(0xffffffffu, s, o);
        q += __shfl_down_sync(0xffffffffu, q, o);
    }
    __shared__ float ss[8], sq[8];
    int wid = tid >> 5, lane = tid & 31;
    if (lane == 0) { ss[wid] = s; sq[wid] = q; }
    __syncthreads();
    float tot = 0.f, totq = 0.f;
    #pragma unroll
    for (int i = 0; i < 8; ++i) { tot += ss[i]; totq += sq[i]; }

    float mu  = tot * (1.0f / DMODEL);
    float var = totq * (1.0f / DMODEL) - mu * mu;
    float rs  = rsqrtf(var + LN_EPS);

    float4 gg = reinterpret_cast<const float4*>(g)[tid];
    float4 bb = reinterpret_cast<const float4*>(b)[tid];
    float4 o;
    o.x = (v.x - mu) * rs * gg.x + bb.x;
    o.y = (v.y - mu) * rs * gg.y + bb.y;
    o.z = (v.z - mu) * rs * gg.z + bb.z;
    o.w = (v.w - mu) * rs * gg.w + bb.w;
    reinterpret_cast<float4*>(y + (size_t)row * DMODEL)[tid] = o;

    uint2 hu;
    hu.x = pack_hf2(o.x, o.y);
    hu.y = pack_hf2(o.z, o.w);
    reinterpret_cast<uint2*>(yh + (size_t)row * DMODEL)[tid] = hu;
}

// ---------------- warp-MMA GEMM (3-stage pipeline) ---------------------------
#define EPI_RES    1
#define EPI_GELUS  2
#define EPI_QKV3   5

#define GROWB  80
#define MATB   (128 * GROWB)
#define OFF_A  0
#define OFF_W  MATB
#define STAGEB (2*MATB)        // 20480
#define GEMM_SMEM (3*STAGEB)   // 61440 -> 2 CTAs = 122880

template<int EPI>
__global__ __launch_bounds__(256, 2)
void gemm_mma(const __half* __restrict__ A, const __half* __restrict__ W,
              const float* __restrict__ bias, const float* __restrict__ res,
              float* __restrict__ Cf, __half* __restrict__ Chi,
              __half* __restrict__ C2, __half* __restrict__ C3,
              int M, int N, int K)
{
    extern __shared__ char smc[];
    uint32_t sb = smem_to_u32(smc);
    int tid  = threadIdx.x;
    int lane = tid & 31;
    int warp = tid >> 5;
    int n0 = blockIdx.x * 128;
    int m0 = blockIdx.y * 128;
    int wm = (warp >> 2) * 64;
    int wn = (warp & 3) * 32;

    int r  = tid >> 1;
    int hf = tid & 1;
    const __half* gA = A + (size_t)(m0 + r) * K + hf * 16;
    const __half* gW = W + (size_t)(n0 + r) * K + hf * 16;
    uint32_t sdst = sb + r * GROWB + hf * 32;

    float acc[4][4][4];
    #pragma unroll
    for (int mi = 0; mi < 4; ++mi)
        #pragma unroll
        for (int nj = 0; nj < 4; ++nj)
            #pragma unroll
            for (int e = 0; e < 4; ++e) acc[mi][nj][e] = 0.f;

    uint32_t lmo = (uint32_t)((lane & 15) * GROWB + (lane >> 4) * 16);
    int nch = K / 32;

    // prologue: stages 0 and 1, each its own group
    {
        cp16(sdst + OFF_A, gA);  cp16(sdst + OFF_A + 16, gA + 8);
        cp16(sdst + OFF_W, gW);  cp16(sdst + OFF_W + 16, gW + 8);
        CP_COMMIT();
        uint32_t d2 = sdst + STAGEB;
        cp16(d2 + OFF_A, gA + 32);  cp16(d2 + OFF_A + 16, gA + 40);
        cp16(d2 + OFF_W, gW + 32);  cp16(d2 + OFF_W + 16, gW + 40);
        CP_COMMIT();
    }

    int cs = 0;
    for (int c = 0; c < nch; ++c) {
        CP_WAIT1();            // stage c landed (per-thread)
        __syncthreads();       // visible to all; all warps done with stage c-1

        // prefetch stage c+2 (empty commit on tail keeps wait invariant)
        if (c + 2 < nch) {
            int ps = cs + 2; if (ps >= 3) ps -= 3;
            size_t ko = (size_t)(c + 2) * 32;
            uint32_t d2 = sdst + ps * STAGEB;
            cp16(d2 + OFF_A, gA + ko);  cp16(d2 + OFF_A + 16, gA + ko + 8);
            cp16(d2 + OFF_W, gW + ko);  cp16(d2 + OFF_W + 16, gW + ko + 8);
        }
        CP_COMMIT();

        uint32_t stgb = sb + cs * STAGEB;
        #pragma unroll
        for (int ks = 0; ks < 2; ++ks) {
            uint32_t kb = ks * 32;
            uint32_t aF[4][4], bW[2][4];
            #pragma unroll
            for (int mi = 0; mi < 4; ++mi) {
                uint32_t ra = (wm + mi * 16) * GROWB + lmo + kb;
                ldsm4(aF[mi], stgb + OFF_A + ra);
            }
            #pragma unroll
            for (int p = 0; p < 2; ++p) {
                uint32_t rb = (wn + p * 16) * GROWB + lmo + kb;
                ldsm4(bW[p], stgb + OFF_W + rb);
            }
            #pragma unroll
            for (int mi = 0; mi < 4; ++mi) {
                #pragma unroll
                for (int nj = 0; nj < 4; ++nj) {
                    uint32_t b0 = bW[nj >> 1][nj & 1];
                    uint32_t b1 = bW[nj >> 1][(nj & 1) + 2];
                    mma16816(acc[mi][nj], aF[mi], b0, b1);
                }
            }
        }
        cs = (cs + 1 == 3) ? 0 : cs + 1;
    }

    int gid  = lane >> 2;
    int tid4 = lane & 3;
    float b2v[4][2];
    #pragma unroll
    for (int nj = 0; nj < 4; ++nj) {
        int col = n0 + wn + nj * 8 + tid4 * 2;
        b2v[nj][0] = bias[col];
        b2v[nj][1] = bias[col + 1];
    }
    __half* qdst = Chi;
    if (EPI == EPI_QKV3) {
        qdst = (n0 < DMODEL) ? Chi : ((n0 < 2*DMODEL) ? C2 : C3);
    }
    #pragma unroll
    for (int mi = 0; mi < 4; ++mi) {
        #pragma unroll
        for (int half = 0; half < 2; ++half) {
            int row = m0 + wm + mi * 16 + gid + half * 8;
            #pragma unroll
            for (int nj = 0; nj < 4; ++nj) {
                int col = n0 + wn + nj * 8 + tid4 * 2;
                float v0 = acc[mi][nj][half * 2 + 0] + b2v[nj][0];
                float v1 = acc[mi][nj][half * 2 + 1] + b2v[nj][1];
                if (EPI == EPI_RES) {
                    float2 rv = *reinterpret_cast<const float2*>(&res[(size_t)row * N + col]);
                    v0 += rv.x; v1 += rv.y;
                    float2 o; o.x = v0; o.y = v1;
                    *reinterpret_cast<float2*>(&Cf[(size_t)row * N + col]) = o;
                } else if (EPI == EPI_QKV3) {
                    int lcol = col & (DMODEL - 1);
                    *reinterpret_cast<uint32_t*>(&qdst[(size_t)row * DMODEL + lcol]) = pack_hf2(v0, v1);
                } else {
                    if (EPI == EPI_GELUS) { v0 = gelu_exact(v0); v1 = gelu_exact(v1); }
                    *reinterpret_cast<uint32_t*>(&Chi[(size_t)row * N + col]) = pack_hf2(v0, v1);
                }
            }
        }
    }
}

// ---------------- MMA flash attention (3-stage KV pipeline) ------------------
#define QST 72                         // smem row stride in fp16 elems (144B)
#define AQ  0
#define AKV0 (128*QST)                 // stage base
#define KVSTG (2*64*QST)               // elems per stage (K, V)
#define AOF_K 0
#define AOF_V (64*QST)
#define ATTN_SMEM ((128*QST + 3*KVSTG) * 2)   // 73728 bytes -> 2 CTAs = 147456

__global__ __launch_bounds__(256, 2)
void attn_mma(const __half* __restrict__ Qh, const __half* __restrict__ Kh,
              const __half* __restrict__ Vh, __half* __restrict__ Ohi)
{
    extern __shared__ __half sma[];
    uint32_t sb = smem_to_u32(sma);

    int tid  = threadIdx.x;
    int lane = tid & 31;
    int warp = tid >> 5;
    int bh = blockIdx.y;
    int b = bh >> 4, h = bh & 15;
    int qbase  = b * SEQ + blockIdx.x * 128;
    int kvbase = b * SEQ;
    int hcol   = h * HDIM;
    int wm = warp * 16;

    // ---- KV loader mapping ----
    int krr = tid >> 2;
    int kc4 = (tid & 3) * 16;
    uint32_t kdst = sb + (krr * QST + kc4) * 2;
    size_t kgo = (size_t)hcol + kc4;

    // prologue: Q + KV stage 0 (group), KV stage 1 (group)
    {
        int rr = tid >> 1, cc2 = (tid & 1) * 4;
        const __half* gq = Qh + (size_t)(qbase + rr) * DMODEL + hcol + cc2 * 8;
        uint32_t dq = sb + (rr * QST + cc2 * 8) * 2;
        #pragma unroll
        for (int c = 0; c < 4; ++c)
            cp16(dq + AQ * 2 + c * 16, gq + c * 8);

        size_t grow = (size_t)(kvbase + krr) * DMODEL + kgo;
        uint32_t st = kdst + AKV0 * 2;
        cp16(st + AOF_K*2, Kh + grow);  cp16(st + AOF_K*2 + 16, Kh + grow + 8);
        cp16(st + AOF_V*2, Vh + grow);  cp16(st + AOF_V*2 + 16, Vh + grow + 8);
        CP_COMMIT();

        grow = (size_t)(kvbase + 64 + krr) * DMODEL + kgo;
        st = kdst + (AKV0 + KVSTG) * 2;
        cp16(st + AOF_K*2, Kh + grow);  cp16(st + AOF_K*2 + 16, Kh + grow + 8);
        cp16(st + AOF_V*2, Vh + grow);  cp16(st + AOF_V*2 + 16, Vh + grow + 8);
        CP_COMMIT();
    }

    float oacc[8][4];
    #pragma unroll
    for (int j = 0; j < 8; ++j)
        #pragma unroll
        for (int e = 0; e < 4; ++e) oacc[j][e] = 0.f;
    float mrow[2] = {-1e30f, -1e30f};
    float lrow[2] = {0.f, 0.f};

    uint32_t lmo = (uint32_t)((lane & 15) * QST * 2 + (lane >> 4) * 16);
    const float scale = 0.125f;

    const int NT = SEQ / 64;
    int cs = 0;
    for (int t = 0; t < NT; ++t) {
        CP_WAIT1();
        __syncthreads();

        if (t + 2 < NT) {
            int ps = cs + 2; if (ps >= 3) ps -= 3;
            size_t grow = (size_t)(kvbase + (t + 2) * 64 + krr) * DMODEL + kgo;
            uint32_t st = kdst + (AKV0 + ps * KVSTG) * 2;
            cp16(st + AOF_K*2, Kh + grow);  cp16(st + AOF_K*2 + 16, Kh + grow + 8);
            cp16(st + AOF_V*2, Vh + grow);  cp16(st + AOF_V*2 + 16, Vh + grow + 8);
        }
        CP_COMMIT();

        uint32_t kvb = sb + (AKV0 + cs * KVSTG) * 2;

        float sacc[8][4];
        #pragma unroll
        for (int j = 0; j < 8; ++j)
            #pragma unroll
            for (int e = 0; e < 4; ++e) sacc[j][e] = 0.f;

        #pragma unroll
        for (int kk = 0; kk < 4; ++kk) {
            uint32_t aQ[4], bK[4];
            uint32_t qa = sb + wm * QST * 2 + lmo + kk * 32;
            ldsm4(aQ, qa + AQ * 2);
            #pragma unroll
            for (int p = 0; p < 4; ++p) {
                uint32_t ka = kvb + p * 16 * QST * 2 + lmo + kk * 32;
                ldsm4(bK, ka + AOF_K * 2);
                #pragma unroll
                for (int tt = 0; tt < 2; ++tt) {
                    int j = p * 2 + tt;
                    mma16816(sacc[j], aQ, bK[tt], bK[tt + 2]);
                }
            }
        }

        float alpha[2];
        #pragma unroll
        for (int hf = 0; hf < 2; ++hf) {
            float mv = mrow[hf];
            #pragma unroll
            for (int j = 0; j < 8; ++j) {
                sacc[j][2*hf]   *= scale;
                sacc[j][2*hf+1] *= scale;
                mv = fmaxf(mv, fmaxf(sacc[j][2*hf], sacc[j][2*hf+1]));
            }
            mv = fmaxf(mv, __shfl_xor_sync(0xffffffffu, mv, 1));
            mv = fmaxf(mv, __shfl_xor_sync(0xffffffffu, mv, 2));
            alpha[hf] = __expf(mrow[hf] - mv);
            float ls = 0.f;
            #pragma unroll
            for (int j = 0; j < 8; ++j) {
                sacc[j][2*hf]   = __expf(sacc[j][2*hf]   - mv);
                sacc[j][2*hf+1] = __expf(sacc[j][2*hf+1] - mv);
                ls += sacc[j][2*hf] + sacc[j][2*hf+1];
            }
            ls += __shfl_xor_sync(0xffffffffu, ls, 1);
            ls += __shfl_xor_sync(0xffffffffu, ls, 2);
            lrow[hf] = lrow[hf] * alpha[hf] + ls;
            mrow[hf] = mv;
            #pragma unroll
            for (int j = 0; j < 8; ++j) {
                oacc[j][2*hf]   *= alpha[hf];
                oacc[j][2*hf+1] *= alpha[hf];
            }
        }

        uint32_t pF[4][4];
        #pragma unroll
        for (int kk = 0; kk < 4; ++kk) {
            int j0 = 2 * kk, j1 = 2 * kk + 1;
            pF[kk][0] = pack_hf2(sacc[j0][0], sacc[j0][1]);
            pF[kk][1] = pack_hf2(sacc[j0][2], sacc[j0][3]);
            pF[kk][2] = pack_hf2(sacc[j1][0], sacc[j1][1]);
            pF[kk][3] = pack_hf2(sacc[j1][2], sacc[j1][3]);
        }

        #pragma unroll
        for (int kk = 0; kk < 4; ++kk) {
            #pragma unroll
            for (int p = 0; p < 4; ++p) {
                uint32_t va = kvb + kk * 16 * QST * 2 + lmo + p * 32;
                uint32_t vV[4];
                ldsm4t(vV, va + AOF_V * 2);
                #pragma unroll
                for (int tt = 0; tt < 2; ++tt) {
                    int j = p * 2 + tt;
                    mma16816(oacc[j], pF[kk], vV[tt * 2], vV[tt * 2 + 1]);
                }
            }
        }
        cs = (cs + 1 == 3) ? 0 : cs + 1;
    }

    #pragma unroll
    for (int hf = 0; hf < 2; ++hf) {
        float il = 1.0f / lrow[hf];
        int row = qbase + wm + (lane >> 2) + hf * 8;
        #pragma unroll
        for (int j = 0; j < 8; ++j) {
            int col = hcol + j * 8 + (lane & 3) * 2;
            float v0 = oacc[j][2*hf]   * il;
            float v1 = oacc[j][2*hf+1] * il;
            *reinterpret_cast<uint32_t*>(&Ohi[(size_t)row * DMODEL + col]) = pack_hf2(v0, v1);
        }
    }
}

// ---------------- launch ----------------------------------------------------
extern "C" void kernel_launch(void* const* d_in, const int* in_sizes, int n_in,
                              void* d_out, int out_size)
{
    (void)in_sizes; (void)n_in; (void)out_size;
    const float* x    = (const float*)d_in[0];
    const float* wq   = (const float*)d_in[1];
    const float* bq   = (const float*)d_in[2];
    const float* wk   = (const float*)d_in[3];
    const float* bk   = (const float*)d_in[4];
    const float* wv   = (const float*)d_in[5];
    const float* bv   = (const float*)d_in[6];
    const float* wo   = (const float*)d_in[7];
    const float* bo   = (const float*)d_in[8];
    const float* ln1g = (const float*)d_in[9];
    const float* ln1b = (const float*)d_in[10];
    const float* w1   = (const float*)d_in[11];
    const float* b1   = (const float*)d_in[12];
    const float* w2   = (const float*)d_in[13];
    const float* b2   = (const float*)d_in[14];
    const float* ln2g = (const float*)d_in[15];
    const float* ln2b = (const float*)d_in[16];
    float* out = (float*)d_out;

    float *xn, *r1, *y, *bqkv;
    cudaGetSymbolAddress((void**)&xn, g_xn);
    cudaGetSymbolAddress((void**)&r1, g_r1);
    cudaGetSymbolAddress((void**)&y,  g_y);
    cudaGetSymbolAddress((void**)&bqkv, g_bqkv);

    __half *xnh,*yh,*qh,*kh,*vh,*ath,*hh;
    __half *wqkvh,*woh,*w1h,*w2h;
    cudaGetSymbolAddress((void**)&xnh, g_xnh);
    cudaGetSymbolAddress((void**)&yh,  g_yh);
    cudaGetSymbolAddress((void**)&qh,  g_qh);
    cudaGetSymbolAddress((void**)&kh,  g_kh);
    cudaGetSymbolAddress((void**)&vh,  g_vh);
    cudaGetSymbolAddress((void**)&ath, g_ath);
    cudaGetSymbolAddress((void**)&hh,  g_hh);
    cudaGetSymbolAddress((void**)&wqkvh, g_wqkvh);
    cudaGetSymbolAddress((void**)&woh, g_woh);
    cudaGetSymbolAddress((void**)&w1h, g_w1h);
    cudaGetSymbolAddress((void**)&w2h, g_w2h);

    cudaFuncSetAttribute(attn_mma, cudaFuncAttributeMaxDynamicSharedMemorySize, ATTN_SMEM);
    cudaFuncSetAttribute(gemm_mma<EPI_QKV3>,  cudaFuncAttributeMaxDynamicSharedMemorySize, GEMM_SMEM);
    cudaFuncSetAttribute(gemm_mma<EPI_RES>,   cudaFuncAttributeMaxDynamicSharedMemorySize, GEMM_SMEM);
    cudaFuncSetAttribute(gemm_mma<EPI_GELUS>, cudaFuncAttributeMaxDynamicSharedMemorySize, GEMM_SMEM);

    conv_qkv_kernel<<<(3*DD4 + 255)/256, 256>>>(wq, wk, wv, bq, bk, bv, wqkvh, bqkv);
    conv_rest_kernel<<<(DD4 + 2*FD4 + 255)/256, 256>>>(wo, w1, w2, woh, w1h, w2h);

    dim3 gQKV(3*DMODEL/128, MROWS/128);   // 24 x 32
    dim3 gD(DMODEL/128, MROWS/128);       // 8 x 32
    dim3 gF(FFDIM/128,  MROWS/128);       // 32 x 32

    ln_conv_kernel<<<MROWS, 256>>>(x, ln1g, ln1b, xn, xnh);
    gemm_mma<EPI_QKV3><<<gQKV, 256, GEMM_SMEM>>>(xnh, wqkvh, bqkv, nullptr, nullptr, qh, kh, vh, MROWS, 3*DMODEL, DMODEL);
    attn_mma<<<dim3(SEQ/128, BATCH*NHEAD), 256, ATTN_SMEM>>>(qh, kh, vh, ath);
    gemm_mma<EPI_RES><<<gD, 256, GEMM_SMEM>>>(ath, woh, bo, xn, r1, nullptr, nullptr, nullptr, MROWS, DMODEL, DMODEL);
    ln_conv_kernel<<<MROWS, 256>>>(r1, ln2g, ln2b, y, yh);
    gemm_mma<EPI_GELUS><<<gF, 256, GEMM_SMEM>>>(yh, w1h, b1, nullptr, nullptr, hh, nullptr, nullptr, MROWS, FFDIM, DMODEL);
    gemm_mma<EPI_RES><<<gD, 256, GEMM_SMEM>>>(hh, w2h, b2, y, out, nullptr, nullptr, nullptr, MROWS, DMODEL, FFDIM);
}